// round 15
// baseline (speedup 1.0000x reference)
#include <cuda_runtime.h>
#include <cuda_fp16.h>
#include <math.h>

// ---------------------------------------------------------------------------
// StylePredictor forward: B=16, T=1024, D=256, H=2, DK=128, convK=5
// FP16 tensor-core GEMMs (mma.sync.m16n8k16, fp32 accumulate), cp.async
// 4-stage pipeline, BK=32, ldmatrix fragment loads. Conv uses a dedicated
// 4-warp kernel with 64x64 warp tiles (3x less smem traffic per MMA).
// No-max flash attention; conv GLU fused; V transposed; QKV one launch;
// masked mean-pool fused into Wo epilogue.
// ---------------------------------------------------------------------------

constexpr int Bn  = 16;
constexpr int Tn  = 1024;
constexpr int Dn  = 256;
constexpr int Hn  = 2;
constexpr int Kc  = 5;
constexpr int Mn  = Bn * Tn;                 // 16384 rows
constexpr float SCALE_ATTN = 1.0f / 16.0f;   // 1/sqrt(256)

constexpr int ROW_B   = 80;                  // GEMM smem row stride (bytes)
constexpr int TILE_B  = 128 * ROW_B;         // 10240
constexpr int STAGES  = 4;
constexpr int SMEM_SZ = 2 * STAGES * TILE_B; // 81920 -> 2 CTA/SM

// flash tiles: 128 rows x 128 halves (256B) padded to 272B
constexpr int FROW_B  = 272;
constexpr int FTILE_B = 128 * FROW_B;        // 34816
constexpr int FK_OFF  = FTILE_B;             // K double buffer
constexpr int FV_OFF  = 3 * FTILE_B;         // V double buffer
constexpr int FSMEM   = 5 * FTILE_B;         // 174080 -> 1 CTA/SM

__device__ __half g_xh[Mn * Dn];
__device__ __half g_h1[Mn * Dn];
__device__ __half g_h2[Mn * Dn];
__device__ __half g_h3[Mn * Dn];
__device__ __half g_res[Mn * Dn];
__device__ __half g_qk[Mn * 2 * Dn];
__device__ __half g_vt[Mn * Dn];             // [bh][128 d][1024 t]
__device__ __half g_attn[Mn * Dn];
__device__ __half g_wt1[2 * Dn * Kc * Dn];   // [512 j][1280 k] interleaved a/g
__device__ __half g_wt2[2 * Dn * Kc * Dn];
__device__ __half g_w1h[Dn * Dn];
__device__ __half g_w2h[Dn * Dn];
__device__ __half g_woh[Dn * Dn];
__device__ __half g_wqkv[3 * Dn * Dn];       // rows: q 0..255, k 256..511, v 512..767
__device__ float  g_bqkv[3 * Dn];
__device__ float  g_Sp[8][Bn * Dn];
__device__ float  g_cinv[Bn];
__device__ unsigned char g_mask[Mn];

// mish(x) = x * tanh(softplus(x)) = x * (t^2 + 2t) / (t^2 + 2t + 2), t = e^x
__device__ __forceinline__ float mishf(float x) {
    if (x > 20.f) return x;
    float t = __expf(x);
    float u = t * t + 2.f * t;
    return x * __fdividef(u, u + 2.f);
}
__device__ __forceinline__ float sigmoidf(float x) {
    return 1.f / (1.f + __expf(-x));
}
__device__ __forceinline__ unsigned pack2(float a, float b) {
    __half2 h = __floats2half2_rn(a, b);
    return *(unsigned*)&h;
}
__device__ __forceinline__ void mma_f16(float* c, const unsigned* a,
                                        const unsigned* b) {
    asm volatile(
        "mma.sync.aligned.m16n8k16.row.col.f32.f16.f16.f32 "
        "{%0,%1,%2,%3}, {%4,%5,%6,%7}, {%8,%9}, {%0,%1,%2,%3};"
        : "+f"(c[0]), "+f"(c[1]), "+f"(c[2]), "+f"(c[3])
        : "r"(a[0]), "r"(a[1]), "r"(a[2]), "r"(a[3]), "r"(b[0]), "r"(b[1]));
}
__device__ __forceinline__ void ldsm4(unsigned* r, unsigned saddr) {
    asm volatile(
        "ldmatrix.sync.aligned.m8n8.x4.shared.b16 {%0,%1,%2,%3}, [%4];"
        : "=r"(r[0]), "=r"(r[1]), "=r"(r[2]), "=r"(r[3]) : "r"(saddr));
}
__device__ __forceinline__ void cpa16(void* dst, const void* g) {
    unsigned s = (unsigned)__cvta_generic_to_shared(dst);
    asm volatile("cp.async.ca.shared.global [%0], [%1], 16;"
                 :: "r"(s), "l"(g) : "memory");
}
__device__ __forceinline__ void cpa16p(void* dst, const void* g, bool ok) {
    unsigned s = (unsigned)__cvta_generic_to_shared(dst);
    int sz = ok ? 16 : 0;
    asm volatile("cp.async.ca.shared.global [%0], [%1], 16, %2;"
                 :: "r"(s), "l"(g), "r"(sz) : "memory");
}

// ---------------------------------------------------------------------------
// Merged prep: fp32->fp16 conversions + weight packing + mask normalization
// (block 7360) in ONE launch.
// ---------------------------------------------------------------------------
__device__ __forceinline__ void cvt8(const float* __restrict__ src,
                                     __half* __restrict__ dst, int i) {
    float4 a = *(const float4*)(src + i);
    float4 b = *(const float4*)(src + i + 4);
    __half2 hh[4] = { __floats2half2_rn(a.x, a.y), __floats2half2_rn(a.z, a.w),
                      __floats2half2_rn(b.x, b.y), __floats2half2_rn(b.z, b.w) };
    *(uint4*)(dst + i) = *(const uint4*)hh;
}

__global__ void prep_all(const float* __restrict__ x,
                         const float* __restrict__ W1,
                         const float* __restrict__ W2,
                         const float* __restrict__ Wo,
                         const float* __restrict__ Wq,
                         const float* __restrict__ Wk,
                         const float* __restrict__ Wv,
                         const float* __restrict__ bq,
                         const float* __restrict__ bk,
                         const float* __restrict__ bv,
                         const float* __restrict__ cW1,
                         const float* __restrict__ cW2,
                         const unsigned char* __restrict__ mraw) {
    __shared__ int s_nz1, s_f3;
    int blk = blockIdx.x, tid = threadIdx.x;
    if (blk < 2144) {
        const float* src;
        __half* dst;
        int base;
        if (blk < 2048)      { src = x;  dst = g_xh;  base = blk; }
        else if (blk < 2080) { src = W1; dst = g_w1h; base = blk - 2048; }
        else if (blk < 2112) { src = W2; dst = g_w2h; base = blk - 2080; }
        else                 { src = Wo; dst = g_woh; base = blk - 2112; }
        cvt8(src, dst, (base * 256 + tid) * 8);
    } else if (blk < 2240) {
        int i = ((blk - 2144) * 256 + tid) * 8;          // 0..196607
        int which = i >> 16;
        const float* src = (which == 0) ? Wq : (which == 1 ? Wk : Wv);
        int j = i & 65535;
        float4 a = *(const float4*)(src + j);
        float4 b = *(const float4*)(src + j + 4);
        __half2 hh[4] = { __floats2half2_rn(a.x, a.y),
                          __floats2half2_rn(a.z, a.w),
                          __floats2half2_rn(b.x, b.y),
                          __floats2half2_rn(b.z, b.w) };
        *(uint4*)(g_wqkv + i) = *(const uint4*)hh;
        if (blk == 2144) {
            g_bqkv[tid] = bq[tid];
            g_bqkv[256 + tid] = bk[tid];
            g_bqkv[512 + tid] = bv[tid];
        }
    } else if (blk < 7360) {
        int rel = blk - 2240;
        const float* cW = cW1;
        __half* Wt = g_wt1;
        if (rel >= 2560) { rel -= 2560; cW = cW2; Wt = g_wt2; }
        int idx = rel * 256 + tid;
        int j = idx / (Kc * Dn);
        int k = idx - j * (Kc * Dn);
        int kk = k >> 8;
        int ic = k & 255;
        int oc = (j & 1) ? (256 + (j >> 1)) : (j >> 1);
        Wt[idx] = __float2half_rn(cW[((size_t)oc * Dn + ic) * Kc + kk]);
    } else {
        // mask normalization + per-batch 1/len (single block)
        if (tid == 0) { s_nz1 = 0; s_f3 = 0; }
        __syncthreads();
        int lnz = 0, lf = 0;
        for (int i = tid; i < Mn; i += 256) {
            unsigned char v = mraw[i];
            if ((i & 3) != 0 && v != 0) lnz++;
            if ((i & 3) == 3 && v == 0x3F) lf++;
        }
        atomicAdd(&s_nz1, lnz);
        atomicAdd(&s_f3, lf);
        __syncthreads();
        int mode = (s_f3 > 0) ? 2 : ((s_nz1 > 0) ? 0 : 1);  // 0=u8 1=i32 2=f32
        for (int i = tid; i < Mn; i += 256) {
            unsigned char m;
            if (mode == 0)      m = (mraw[i] != 0);
            else if (mode == 1) m = (((const int*)mraw)[i] != 0);
            else                m = (((const float*)mraw)[i] != 0.f);
            g_mask[i] = m;
        }
        __syncthreads();
        int b = tid >> 4, seg = tid & 15;
        int cnt = 0;
        for (int t = seg * 64; t < seg * 64 + 64; t++)
            cnt += (g_mask[b * Tn + t] == 0);
#pragma unroll
        for (int o = 1; o < 16; o <<= 1)
            cnt += __shfl_xor_sync(0xffffffffu, cnt, o);
        if (seg == 0) g_cinv[b] = 1.f / (float)cnt;
    }
}

// ---------------------------------------------------------------------------
// Conv1dGLU implicit GEMM, 4 warps with 64x64 warp tiles (smem-lean).
// C128x128 tile over [16384 x 512 x 1280]; A rows time-shifted; GLU epilogue.
// ---------------------------------------------------------------------------
template <bool MASKED>
__global__ void __launch_bounds__(128)
conv_gemm(const __half* __restrict__ A, const __half* __restrict__ Bm,
          const float* __restrict__ bias, const __half* __restrict__ res,
          __half* __restrict__ C) {
    extern __shared__ char sm[];             // A[4] then B[4]
    char* smB = sm + STAGES * TILE_B;
    const unsigned smA_s = (unsigned)__cvta_generic_to_shared(sm);
    const unsigned smB_s = smA_s + STAGES * TILE_B;

    const int m0 = blockIdx.y * 128;
    const int n0 = blockIdx.x * 128;
    const int tid  = threadIdx.x;
    const int warp = tid >> 5, lane = tid & 31;
    const int wr = warp >> 1, wc = warp & 1;     // 2 x 2 warp grid, 64x64
    const int gid = lane >> 2, tig = lane & 3;
    const int lr8 = lane & 7;

    unsigned aoff[4], boff[4];
#pragma unroll
    for (int mt = 0; mt < 4; mt++)
        aoff[mt] = (unsigned)((wr * 64 + mt * 16 + lr8 + ((lane >> 3) & 1) * 8)
                   * ROW_B + ((lane >> 4) & 1) * 16);
#pragma unroll
    for (int np = 0; np < 4; np++)
        boff[np] = (unsigned)((wc * 64 + np * 16 + lr8 + ((lane >> 4) & 1) * 8)
                   * ROW_B + ((lane >> 3) & 1) * 16);

    auto load_tiles = [&](int buf, int kt) {
        int dt = (kt >> 8) - 2;
#pragma unroll
        for (int p = 0; p < 4; p++) {
            int idx = tid + p * 128;
            int row = idx >> 2, ch = idx & 3;
            int m = m0 + row;
            int t = m & (Tn - 1);
            bool ok = (unsigned)(t + dt) < (unsigned)Tn;
            const __half* g = A + (size_t)(m + (ok ? dt : 0)) * Dn +
                              (kt & 255) + ch * 8;
            cpa16p(sm + buf * TILE_B + row * ROW_B + ch * 16, g, ok);
            cpa16(smB + buf * TILE_B + row * ROW_B + ch * 16,
                  Bm + (size_t)(n0 + row) * (Kc * Dn) + kt + ch * 8);
        }
    };

    float acc[4][8][4];
#pragma unroll
    for (int i = 0; i < 4; i++)
#pragma unroll
        for (int j = 0; j < 8; j++)
#pragma unroll
            for (int q = 0; q < 4; q++) acc[i][j][q] = 0.f;

    const int nIter = (Kc * Dn) >> 5;            // 40
    load_tiles(0, 0);
    asm volatile("cp.async.commit_group;" ::: "memory");
    load_tiles(1, 32);
    asm volatile("cp.async.commit_group;" ::: "memory");
    load_tiles(2, 64);
    asm volatile("cp.async.commit_group;" ::: "memory");

    for (int it = 0; it < nIter; it++) {
        int buf = it & 3;
        if (it + 2 < nIter) {
            asm volatile("cp.async.wait_group 2;" ::: "memory");
        } else if (it + 1 < nIter) {
            asm volatile("cp.async.wait_group 1;" ::: "memory");
        } else {
            asm volatile("cp.async.wait_group 0;" ::: "memory");
        }
        __syncthreads();
        if (it + 3 < nIter) {
            load_tiles((it + 3) & 3, (it + 3) << 5);
            asm volatile("cp.async.commit_group;" ::: "memory");
        }

        const unsigned baseA = smA_s + buf * TILE_B;
        const unsigned baseB = smB_s + buf * TILE_B;
#pragma unroll
        for (int ks = 0; ks < 2; ks++) {
            unsigned kb = ks * 32;
            unsigned af[4][4];
#pragma unroll
            for (int mt = 0; mt < 4; mt++)
                ldsm4(af[mt], baseA + kb + aoff[mt]);
            unsigned bfr[8][2];
#pragma unroll
            for (int np = 0; np < 4; np++) {
                unsigned bt[4];
                ldsm4(bt, baseB + kb + boff[np]);
                bfr[2 * np][0] = bt[0]; bfr[2 * np][1] = bt[1];
                bfr[2 * np + 1][0] = bt[2]; bfr[2 * np + 1][1] = bt[3];
            }
#pragma unroll
            for (int mt = 0; mt < 4; mt++)
#pragma unroll
                for (int nt = 0; nt < 8; nt++)
                    mma_f16(acc[mt][nt], af[mt], bfr[nt]);
        }
    }

    // ---- GLU epilogue: even n = a, odd n = gate ----
#pragma unroll
    for (int mt = 0; mt < 4; mt++) {
#pragma unroll
        for (int nt = 0; nt < 8; nt++) {
            int n = n0 + wc * 64 + nt * 8 + 2 * tig;
            int i = n >> 1;
#pragma unroll
            for (int half_ = 0; half_ < 2; half_++) {
                int m = m0 + wr * 64 + mt * 16 + gid + half_ * 8;
                float a = acc[mt][nt][half_ * 2 + 0] + bias[i];
                float g = acc[mt][nt][half_ * 2 + 1] + bias[256 + i];
                float v = __half2float(res[(size_t)m * 256 + i]) +
                          a * sigmoidf(g);
                if (MASKED && g_mask[m]) v = 0.f;
                C[(size_t)m * 256 + i] = __float2half_rn(v);
            }
        }
    }
}

// ---------------------------------------------------------------------------
// FP16 tensor-core TN GEMM: C = epi( A[M,K](lda) @ B[N,K](ldb)^T )
// 128x128 tile, BK=32, 256 threads, 4-stage cp.async (1 barrier/iter).
// EPI: 1=mish(+bias) half,
//      8=QKV fused (n<512 -> qk, n>=512 -> vt transpose; res=vt out),
//      9=Wo: +bias+res, masked pool directly into g_Sp (no C store)
// ---------------------------------------------------------------------------
template <int EPI>
__global__ void __launch_bounds__(256)
mma_gemm(const __half* __restrict__ A, const __half* __restrict__ Bm,
         const float* __restrict__ bias, const __half* __restrict__ res,
         void* __restrict__ Cv, int K, int lda, int ldb, int ldc) {
    extern __shared__ char sm[];             // A[4] then B[4]
    char* smB = sm + STAGES * TILE_B;
    const unsigned smA_s = (unsigned)__cvta_generic_to_shared(sm);
    const unsigned smB_s = smA_s + STAGES * TILE_B;

    const int m0 = blockIdx.y * 128;
    const int n0 = blockIdx.x * 128;
    const int tid  = threadIdx.x;
    const int warp = tid >> 5, lane = tid & 31;
    const int wr = warp >> 2, wc = warp & 3;     // 2 x 4 warp grid
    const int gid = lane >> 2, tig = lane & 3;

    const int lr8 = lane & 7;
    unsigned aoff[4], boff[2];
#pragma unroll
    for (int mt = 0; mt < 4; mt++)
        aoff[mt] = (unsigned)((wr * 64 + mt * 16 + lr8 + ((lane >> 3) & 1) * 8)
                   * ROW_B + ((lane >> 4) & 1) * 16);
#pragma unroll
    for (int np = 0; np < 2; np++)
        boff[np] = (unsigned)((wc * 32 + np * 16 + lr8 + ((lane >> 4) & 1) * 8)
                   * ROW_B + ((lane >> 3) & 1) * 16);

    auto load_tiles = [&](int buf, int kt) {
#pragma unroll
        for (int p = 0; p < 2; p++) {
            int idx = tid + p * 256;
            int row = idx >> 2, ch = idx & 3;
            cpa16(sm + buf * TILE_B + row * ROW_B + ch * 16,
                  A + (size_t)(m0 + row) * lda + kt + ch * 8);
            cpa16(smB + buf * TILE_B + row * ROW_B + ch * 16,
                  Bm + (size_t)(n0 + row) * ldb + kt + ch * 8);
        }
    };

    float acc[4][4][4];
#pragma unroll
    for (int i = 0; i < 4; i++)
#pragma unroll
        for (int j = 0; j < 4; j++)
#pragma unroll
            for (int q = 0; q < 4; q++) acc[i][j][q] = 0.f;

    const int nIter = K >> 5;                    // BK = 32 halves, nIter >= 4
    load_tiles(0, 0);
    asm volatile("cp.async.commit_group;" ::: "memory");
    load_tiles(1, 32);
    asm volatile("cp.async.commit_group;" ::: "memory");
    load_tiles(2, 64);
    asm volatile("cp.async.commit_group;" ::: "memory");

    for (int it = 0; it < nIter; it++) {
        int buf = it & 3;
        if (it + 2 < nIter) {
            asm volatile("cp.async.wait_group 2;" ::: "memory");
        } else if (it + 1 < nIter) {
            asm volatile("cp.async.wait_group 1;" ::: "memory");
        } else {
            asm volatile("cp.async.wait_group 0;" ::: "memory");
        }
        __syncthreads();
        if (it + 3 < nIter) {
            load_tiles((it + 3) & 3, (it + 3) << 5);
            asm volatile("cp.async.commit_group;" ::: "memory");
        }

        const unsigned baseA = smA_s + buf * TILE_B;
        const unsigned baseB = smB_s + buf * TILE_B;
#pragma unroll
        for (int ks = 0; ks < 2; ks++) {
            unsigned kb = ks * 32;
            unsigned af[4][4];
#pragma unroll
            for (int mt = 0; mt < 4; mt++)
                ldsm4(af[mt], baseA + kb + aoff[mt]);
            unsigned bfr[4][2];
#pragma unroll
            for (int np = 0; np < 2; np++) {
                unsigned bt[4];
                ldsm4(bt, baseB + kb + boff[np]);
                bfr[2 * np][0] = bt[0]; bfr[2 * np][1] = bt[1];
                bfr[2 * np + 1][0] = bt[2]; bfr[2 * np + 1][1] = bt[3];
            }
#pragma unroll
            for (int mt = 0; mt < 4; mt++)
#pragma unroll
                for (int nt = 0; nt < 4; nt++)
                    mma_f16(acc[mt][nt], af[mt], bfr[nt]);
        }
    }

    // ---- epilogue ----
    if (EPI == 9) {
        float ls[4][2];
#pragma unroll
        for (int nt = 0; nt < 4; nt++) { ls[nt][0] = 0.f; ls[nt][1] = 0.f; }
#pragma unroll
        for (int mt = 0; mt < 4; mt++)
#pragma unroll
            for (int half_ = 0; half_ < 2; half_++) {
                int m = m0 + wr * 64 + mt * 16 + gid + half_ * 8;
                bool keep = (g_mask[m] == 0);
#pragma unroll
                for (int nt = 0; nt < 4; nt++) {
                    int n = n0 + wc * 32 + nt * 8 + 2 * tig;
                    float v0 = acc[mt][nt][half_ * 2 + 0] + bias[n] +
                               __half2float(res[(size_t)m * ldc + n]);
                    float v1 = acc[mt][nt][half_ * 2 + 1] + bias[n + 1] +
                               __half2float(res[(size_t)m * ldc + n + 1]);
                    if (keep) { ls[nt][0] += v0; ls[nt][1] += v1; }
                }
            }
#pragma unroll
        for (int nt = 0; nt < 4; nt++)
#pragma unroll
            for (int c = 0; c < 2; c++) {
                float r = ls[nt][c];
                r += __shfl_xor_sync(0xffffffffu, r, 4);
                r += __shfl_xor_sync(0xffffffffu, r, 8);
                r += __shfl_xor_sync(0xffffffffu, r, 16);
                ls[nt][c] = r;
            }
        __syncthreads();
        float* spf = (float*)sm;
        if (lane < 4) {
#pragma unroll
            for (int nt = 0; nt < 4; nt++) {
                spf[warp * 32 + lane * 8 + nt * 2 + 0] = ls[nt][0];
                spf[warp * 32 + lane * 8 + nt * 2 + 1] = ls[nt][1];
            }
        }
        __syncthreads();
        if (warp < 4) {
            float s = spf[warp * 32 + lane] + spf[(warp + 4) * 32 + lane];
            int tig_ = lane >> 3, nt_ = (lane >> 1) & 3, c_ = lane & 1;
            int n = n0 + warp * 32 + nt_ * 8 + 2 * tig_ + c_;
            int y = m0 >> 7, b = y >> 3, chunk = y & 7;
            g_Sp[chunk][b * Dn + n] = s;
        }
        return;
    }

#pragma unroll
    for (int mt = 0; mt < 4; mt++) {
#pragma unroll
        for (int nt = 0; nt < 4; nt++) {
            int mbase = m0 + wr * 64 + mt * 16 + gid;
            int n = n0 + wc * 32 + nt * 8 + 2 * tig;
#pragma unroll
            for (int half_ = 0; half_ < 2; half_++) {
                int m = mbase + half_ * 8;
                float v0 = acc[mt][nt][half_ * 2 + 0];
                float v1 = acc[mt][nt][half_ * 2 + 1];
                if (EPI == 8) {
                    v0 += bias[n]; v1 += bias[n + 1];
                    if (n0 < 512) {              // q,k region
                        __half* C = (__half*)Cv;
                        *(__half2*)(C + (size_t)m * 512 + n) =
                            __floats2half2_rn(v0, v1);
                    } else {                     // v region -> transposed store
                        __half* VT = (__half*)(void*)res;
                        int bb = m >> 10, t = m & (Tn - 1);
                        int d = n - 512;
                        VT[((size_t)((bb * 2 + (d >> 7)) * 128 + (d & 127))) * Tn + t] =
                            __float2half_rn(v0);
                        d = n + 1 - 512;
                        VT[((size_t)((bb * 2 + (d >> 7)) * 128 + (d & 127))) * Tn + t] =
                            __float2half_rn(v1);
                    }
                } else {                          // EPI == 1 (mish)
                    __half* C = (__half*)Cv;
                    v0 = mishf(v0 + bias[n]);
                    v1 = mishf(v1 + bias[n + 1]);
                    *(__half2*)(C + (size_t)m * ldc + n) =
                        __floats2half2_rn(v0, v1);
                }
            }
        }
    }
}

// ---------------------------------------------------------------------------
// Fused attention (no-max flash). Grid (8 q-tiles, 32 bh), 256 threads.
// ---------------------------------------------------------------------------
__global__ void __launch_bounds__(256)
flash_kernel(const __half* __restrict__ qk, const __half* __restrict__ vt,
             __half* __restrict__ attn) {
    const int qt = blockIdx.x;
    const int z  = blockIdx.y;
    const int zb = z >> 1, zh = z & 1;
    extern __shared__ char sm[];
    const unsigned smQ = (unsigned)__cvta_generic_to_shared(sm);
    const int tid = threadIdx.x, warp = tid >> 5, lane = tid & 31;
    const int gid = lane >> 2, tig = lane & 3, lr8 = lane & 7;

    const unsigned aoffQ = (unsigned)((warp * 16 + lr8 + ((lane >> 3) & 1) * 8)
                           * FROW_B + ((lane >> 4) & 1) * 16);
    unsigned boffF[8];
#pragma unroll
    for (int np = 0; np < 8; np++)
        boffF[np] = (unsigned)((np * 16 + lr8 + ((lane >> 4) & 1) * 8)
                    * FROW_B + ((lane >> 3) & 1) * 16);

    auto loadQ = [&]() {
#pragma unroll
        for (int p = 0; p < 8; p++) {
            int idx = tid + p * 256;
            int row = idx >> 4, ch = idx & 15;
            cpa16(sm + row * FROW_B + ch * 16,
                  qk + (size_t)(zb * Tn + qt * 128 + row) * 512 +
                  zh * 128 + ch * 8);
        }
    };
    auto loadK = [&](int buf, int jt) {
#pragma unroll
        for (int p = 0; p < 8; p++) {
            int idx = tid + p * 256;
            int row = idx >> 4, ch = idx & 15;
            cpa16(sm + FK_OFF + buf * FTILE_B + row * FROW_B + ch * 16,
                  qk + (size_t)(zb * Tn + jt * 128 + row) * 512 +
                  256 + zh * 128 + ch * 8);
        }
    };
    auto loadV = [&](int buf, int jt) {
#pragma unroll
        for (int p = 0; p < 8; p++) {
            int idx = tid + p * 256;
            int row = idx >> 4, ch = idx & 15;
            cpa16(sm + FV_OFF + buf * FTILE_B + row * FROW_B + ch * 16,
                  vt + (size_t)(z * 128 + row) * Tn + jt * 128 + ch * 8);
        }
    };

    loadQ(); loadK(0, 0); loadV(0, 0);
    asm volatile("cp.async.commit_group;" ::: "memory");

    float O[16][4];
#pragma unroll
    for (int i = 0; i < 16; i++)
#pragma unroll
        for (int q = 0; q < 4; q++) O[i][q] = 0.f;
    float rs0 = 0.f, rs1 = 0.f;
    unsigned qf[8][4];

    for (int jt = 0; jt < 8; jt++) {
        int buf = jt & 1;
        asm volatile("cp.async.wait_group 0;" ::: "memory");
        __syncthreads();
        if (jt < 7) {
            loadK(buf ^ 1, jt + 1);
            loadV(buf ^ 1, jt + 1);
            asm volatile("cp.async.commit_group;" ::: "memory");
        }
        if (jt == 0) {
#pragma unroll
            for (int kd = 0; kd < 8; kd++)
                ldsm4(qf[kd], smQ + kd * 32 + aoffQ);
        }

        float S[16][4];
#pragma unroll
        for (int i = 0; i < 16; i++)
#pragma unroll
            for (int q = 0; q < 4; q++) S[i][q] = 0.f;
        const unsigned baseK = smQ + FK_OFF + buf * FTILE_B;
#pragma unroll
        for (int kd = 0; kd < 8; kd++) {
#pragma unroll
            for (int np = 0; np < 8; np++) {
                unsigned bt[4];
                ldsm4(bt, baseK + kd * 32 + boffF[np]);
                mma_f16(S[2 * np],     qf[kd], bt);
                mma_f16(S[2 * np + 1], qf[kd], bt + 2);
            }
        }

        unsigned P[16][2];
        const unsigned char* mkb = g_mask + zb * Tn + jt * 128;
#pragma unroll
        for (int nt = 0; nt < 16; nt++) {
            int c0 = nt * 8 + 2 * tig;
            bool mA = mkb[c0], mB = mkb[c0 + 1];
            float e0 = mA ? 0.f : __expf(fminf(S[nt][0] * SCALE_ATTN, 15.f));
            float e1 = mB ? 0.f : __expf(fminf(S[nt][1] * SCALE_ATTN, 15.f));
            float e2 = mA ? 0.f : __expf(fminf(S[nt][2] * SCALE_ATTN, 15.f));
            float e3 = mB ? 0.f : __expf(fminf(S[nt][3] * SCALE_ATTN, 15.f));
            rs0 += e0 + e1;
            rs1 += e2 + e3;
            P[nt][0] = pack2(e0, e1);
            P[nt][1] = pack2(e2, e3);
        }

        const unsigned baseV = smQ + FV_OFF + buf * FTILE_B;
#pragma unroll
        for (int s = 0; s < 8; s++) {
            unsigned a2[4] = { P[2 * s][0], P[2 * s][1],
                               P[2 * s + 1][0], P[2 * s + 1][1] };
#pragma unroll
            for (int np = 0; np < 8; np++) {
                unsigned bt[4];
                ldsm4(bt, baseV + s * 32 + boffF[np]);
                mma_f16(O[2 * np],     a2, bt);
                mma_f16(O[2 * np + 1], a2, bt + 2);
            }
        }
    }

    // quad-reduce row sums (each lane holds 2 of every 8 columns)
    rs0 += __shfl_xor_sync(0xffffffffu, rs0, 1);
    rs0 += __shfl_xor_sync(0xffffffffu, rs0, 2);
    rs1 += __shfl_xor_sync(0xffffffffu, rs1, 1);
    rs1 += __shfl_xor_sync(0xffffffffu, rs1, 2);

    float i0 = 1.f / rs0, i1 = 1.f / rs1;
    int t = qt * 128 + warp * 16 + gid;
    __half* dst = attn + (size_t)(zb * Tn + t) * 256 + zh * 128;
#pragma unroll
    for (int nt = 0; nt < 16; nt++) {
        int d = nt * 8 + 2 * tig;
        *(__half2*)(dst + d) = __floats2half2_rn(O[nt][0] * i0, O[nt][1] * i0);
        *(__half2*)(dst + (size_t)8 * 256 + d) =
            __floats2half2_rn(O[nt][2] * i1, O[nt][3] * i1);
    }
}

// out[b,n] = (S_b @ Wf^T)[n]/len_b + bf[n]
__global__ void final_kernel(const float* __restrict__ Wf,
                             const float* __restrict__ bf,
                             float* __restrict__ out) {
    int b = blockIdx.x;
    int n = threadIdx.x;
    __shared__ float sb[Dn];
    float s = 0.f;
#pragma unroll
    for (int c = 0; c < 8; c++) s += g_Sp[c][b * Dn + n];
    sb[n] = s;
    __syncthreads();
    float acc = 0.f;
    const float* w = Wf + (size_t)n * Dn;
#pragma unroll 8
    for (int k = 0; k < Dn; k++) acc = fmaf(sb[k], w[k], acc);
    out[b * Dn + n] = acc * g_cinv[b] + bf[n];
}

// ---------------------------------------------------------------------------
extern "C" void kernel_launch(void* const* d_in, const int* in_sizes, int n_in,
                              void* d_out, int out_size) {
    (void)in_sizes; (void)n_in; (void)out_size;
    const float* x   = (const float*)d_in[0];
    const unsigned char* mraw = (const unsigned char*)d_in[1];
    const float* W1  = (const float*)d_in[2];
    const float* b1  = (const float*)d_in[3];
    const float* W2  = (const float*)d_in[4];
    const float* b2  = (const float*)d_in[5];
    const float* cW1 = (const float*)d_in[6];
    const float* cb1 = (const float*)d_in[7];
    const float* cW2 = (const float*)d_in[8];
    const float* cb2 = (const float*)d_in[9];
    const float* Wq  = (const float*)d_in[10];
    const float* bq  = (const float*)d_in[11];
    const float* Wk  = (const float*)d_in[12];
    const float* bk  = (const float*)d_in[13];
    const float* Wv  = (const float*)d_in[14];
    const float* bv  = (const float*)d_in[15];
    const float* Wo  = (const float*)d_in[16];
    const float* bo  = (const float*)d_in[17];
    const float* Wf  = (const float*)d_in[18];
    const float* bf  = (const float*)d_in[19];
    float* out = (float*)d_out;

    __half *xh, *h1, *h2, *h3, *res, *qk, *vt, *attn;
    __half *wt1, *wt2, *w1h, *w2h, *woh, *wqkv;
    float *bqkv;
    cudaGetSymbolAddress((void**)&xh, g_xh);
    cudaGetSymbolAddress((void**)&h1, g_h1);
    cudaGetSymbolAddress((void**)&h2, g_h2);
    cudaGetSymbolAddress((void**)&h3, g_h3);
    cudaGetSymbolAddress((void**)&res, g_res);
    cudaGetSymbolAddress((void**)&qk, g_qk);
    cudaGetSymbolAddress((void**)&vt, g_vt);
    cudaGetSymbolAddress((void**)&attn, g_attn);
    cudaGetSymbolAddress((void**)&wt1, g_wt1);
    cudaGetSymbolAddress((void**)&wt2, g_wt2);
    cudaGetSymbolAddress((void**)&w1h, g_w1h);
    cudaGetSymbolAddress((void**)&w2h, g_w2h);
    cudaGetSymbolAddress((void**)&woh, g_woh);
    cudaGetSymbolAddress((void**)&wqkv, g_wqkv);
    cudaGetSymbolAddress((void**)&bqkv, g_bqkv);

    cudaFuncSetAttribute(mma_gemm<1>, cudaFuncAttributeMaxDynamicSharedMemorySize, SMEM_SZ);
    cudaFuncSetAttribute(mma_gemm<8>, cudaFuncAttributeMaxDynamicSharedMemorySize, SMEM_SZ);
    cudaFuncSetAttribute(mma_gemm<9>, cudaFuncAttributeMaxDynamicSharedMemorySize, SMEM_SZ);
    cudaFuncSetAttribute(conv_gemm<false>, cudaFuncAttributeMaxDynamicSharedMemorySize, SMEM_SZ);
    cudaFuncSetAttribute(conv_gemm<true>,  cudaFuncAttributeMaxDynamicSharedMemorySize, SMEM_SZ);
    cudaFuncSetAttribute(flash_kernel, cudaFuncAttributeMaxDynamicSharedMemorySize, FSMEM);

    // 0) single merged prep pass (incl. mask normalization block)
    prep_all<<<7361, 256>>>(x, W1, W2, Wo, Wq, Wk, Wv, bq, bk, bv,
                            cW1, cW2, mraw);

    dim3 gDense(2, 128, 1);
    dim3 gConv(4, 128, 1);
    dim3 gQKV(6, 128, 1);
    dim3 gFlash(8, 32, 1);

    // 1) spectral MLP (Linear + Mish) x2
    mma_gemm<1><<<gDense, 256, SMEM_SZ>>>(xh, w1h, b1, nullptr, h1,
        Dn, Dn, Dn, Dn);
    mma_gemm<1><<<gDense, 256, SMEM_SZ>>>(h1, w2h, b2, nullptr, h2,
        Dn, Dn, Dn, Dn);

    // 2) Conv1dGLU x2 (64x64-warp-tile conv kernel, GLU fused)
    conv_gemm<false><<<gConv, 128, SMEM_SZ>>>(h2, wt1, cb1, h2, h3);
    conv_gemm<true><<<gConv, 128, SMEM_SZ>>>(h3, wt2, cb2, h3, res);

    // 3) fused q,k,v projection (N=768; v written transposed via res ptr)
    mma_gemm<8><<<gQKV, 256, SMEM_SZ>>>(res, wqkv, bqkv, vt, qk,
        Dn, Dn, Dn, 512);

    // 4) fused attention (flash, no-max)
    flash_kernel<<<gFlash, 256, FSMEM>>>(qk, vt, attn);

    // 5) output projection + residual with fused masked pool (no h5 store)
    mma_gemm<9><<<gDense, 256, SMEM_SZ>>>(attn, woh, bo, res, nullptr,
        Dn, Dn, Dn, Dn);

    // 6) tiny final GEMM (Wf applied to pooled sums)
    final_kernel<<<Bn, Dn>>>(Wf, bf, out);
}

// round 16
// speedup vs baseline: 1.0725x; 1.0725x over previous
#include <cuda_runtime.h>
#include <cuda_fp16.h>
#include <math.h>

// ---------------------------------------------------------------------------
// StylePredictor forward: B=16, T=1024, D=256, H=2, DK=128, convK=5
// FP16 tensor-core GEMMs (mma.sync.m16n8k16, fp32 accumulate), cp.async
// pipelines, BK=32, ldmatrix fragment loads. Conv keeps A resident in smem
// (132 rows, loaded once; taps addressed by row shift) and streams only B.
// No-max flash attention; conv GLU fused (residual from smem); V transposed;
// QKV one launch; masked mean-pool fused into Wo epilogue.
// ---------------------------------------------------------------------------

constexpr int Bn  = 16;
constexpr int Tn  = 1024;
constexpr int Dn  = 256;
constexpr int Hn  = 2;
constexpr int Kc  = 5;
constexpr int Mn  = Bn * Tn;                 // 16384 rows
constexpr float SCALE_ATTN = 1.0f / 16.0f;   // 1/sqrt(256)

constexpr int ROW_B   = 80;                  // GEMM smem row stride (bytes)
constexpr int TILE_B  = 128 * ROW_B;         // 10240
constexpr int STAGES  = 4;
constexpr int SMEM_SZ = 2 * STAGES * TILE_B; // 81920 -> 2 CTA/SM

// conv: resident A buffer (132 rows x 256 halves, 528B stride) + 3 B stages
constexpr int AROW_B  = 528;
constexpr int ABUF_B  = 132 * AROW_B;        // 69696
constexpr int CSMEM   = ABUF_B + 3 * TILE_B; // 100416 -> 2 CTA/SM

// flash tiles: 128 rows x 128 halves (256B) padded to 272B
constexpr int FROW_B  = 272;
constexpr int FTILE_B = 128 * FROW_B;        // 34816
constexpr int FK_OFF  = FTILE_B;             // K double buffer
constexpr int FV_OFF  = 3 * FTILE_B;         // V double buffer
constexpr int FSMEM   = 5 * FTILE_B;         // 174080 -> 1 CTA/SM

__device__ __half g_xh[Mn * Dn];
__device__ __half g_h1[Mn * Dn];
__device__ __half g_h2[Mn * Dn];
__device__ __half g_h3[Mn * Dn];
__device__ __half g_res[Mn * Dn];
__device__ __half g_qk[Mn * 2 * Dn];
__device__ __half g_vt[Mn * Dn];             // [bh][128 d][1024 t]
__device__ __half g_attn[Mn * Dn];
__device__ __half g_wt1[2 * Dn * Kc * Dn];   // [512 j][1280 k] interleaved a/g
__device__ __half g_wt2[2 * Dn * Kc * Dn];
__device__ __half g_w1h[Dn * Dn];
__device__ __half g_w2h[Dn * Dn];
__device__ __half g_woh[Dn * Dn];
__device__ __half g_wqkv[3 * Dn * Dn];       // rows: q 0..255, k 256..511, v 512..767
__device__ float  g_bqkv[3 * Dn];
__device__ float  g_Sp[8][Bn * Dn];
__device__ float  g_cinv[Bn];
__device__ unsigned char g_mask[Mn];

// mish(x) = x * tanh(softplus(x)) = x * (t^2 + 2t) / (t^2 + 2t + 2), t = e^x
__device__ __forceinline__ float mishf(float x) {
    if (x > 20.f) return x;
    float t = __expf(x);
    float u = t * t + 2.f * t;
    return x * __fdividef(u, u + 2.f);
}
__device__ __forceinline__ float sigmoidf(float x) {
    return 1.f / (1.f + __expf(-x));
}
__device__ __forceinline__ unsigned pack2(float a, float b) {
    __half2 h = __floats2half2_rn(a, b);
    return *(unsigned*)&h;
}
__device__ __forceinline__ void mma_f16(float* c, const unsigned* a,
                                        const unsigned* b) {
    asm volatile(
        "mma.sync.aligned.m16n8k16.row.col.f32.f16.f16.f32 "
        "{%0,%1,%2,%3}, {%4,%5,%6,%7}, {%8,%9}, {%0,%1,%2,%3};"
        : "+f"(c[0]), "+f"(c[1]), "+f"(c[2]), "+f"(c[3])
        : "r"(a[0]), "r"(a[1]), "r"(a[2]), "r"(a[3]), "r"(b[0]), "r"(b[1]));
}
__device__ __forceinline__ void ldsm4(unsigned* r, unsigned saddr) {
    asm volatile(
        "ldmatrix.sync.aligned.m8n8.x4.shared.b16 {%0,%1,%2,%3}, [%4];"
        : "=r"(r[0]), "=r"(r[1]), "=r"(r[2]), "=r"(r[3]) : "r"(saddr));
}
__device__ __forceinline__ void cpa16(void* dst, const void* g) {
    unsigned s = (unsigned)__cvta_generic_to_shared(dst);
    asm volatile("cp.async.ca.shared.global [%0], [%1], 16;"
                 :: "r"(s), "l"(g) : "memory");
}
__device__ __forceinline__ void cpa16p(void* dst, const void* g, bool ok) {
    unsigned s = (unsigned)__cvta_generic_to_shared(dst);
    int sz = ok ? 16 : 0;
    asm volatile("cp.async.ca.shared.global [%0], [%1], 16, %2;"
                 :: "r"(s), "l"(g), "r"(sz) : "memory");
}

// ---------------------------------------------------------------------------
// Merged prep: fp32->fp16 conversions + weight packing + mask normalization
// (block 7360) in ONE launch.
// ---------------------------------------------------------------------------
__device__ __forceinline__ void cvt8(const float* __restrict__ src,
                                     __half* __restrict__ dst, int i) {
    float4 a = *(const float4*)(src + i);
    float4 b = *(const float4*)(src + i + 4);
    __half2 hh[4] = { __floats2half2_rn(a.x, a.y), __floats2half2_rn(a.z, a.w),
                      __floats2half2_rn(b.x, b.y), __floats2half2_rn(b.z, b.w) };
    *(uint4*)(dst + i) = *(const uint4*)hh;
}

__global__ void prep_all(const float* __restrict__ x,
                         const float* __restrict__ W1,
                         const float* __restrict__ W2,
                         const float* __restrict__ Wo,
                         const float* __restrict__ Wq,
                         const float* __restrict__ Wk,
                         const float* __restrict__ Wv,
                         const float* __restrict__ bq,
                         const float* __restrict__ bk,
                         const float* __restrict__ bv,
                         const float* __restrict__ cW1,
                         const float* __restrict__ cW2,
                         const unsigned char* __restrict__ mraw) {
    __shared__ int s_nz1, s_f3;
    int blk = blockIdx.x, tid = threadIdx.x;
    if (blk < 2144) {
        const float* src;
        __half* dst;
        int base;
        if (blk < 2048)      { src = x;  dst = g_xh;  base = blk; }
        else if (blk < 2080) { src = W1; dst = g_w1h; base = blk - 2048; }
        else if (blk < 2112) { src = W2; dst = g_w2h; base = blk - 2080; }
        else                 { src = Wo; dst = g_woh; base = blk - 2112; }
        cvt8(src, dst, (base * 256 + tid) * 8);
    } else if (blk < 2240) {
        int i = ((blk - 2144) * 256 + tid) * 8;          // 0..196607
        int which = i >> 16;
        const float* src = (which == 0) ? Wq : (which == 1 ? Wk : Wv);
        int j = i & 65535;
        float4 a = *(const float4*)(src + j);
        float4 b = *(const float4*)(src + j + 4);
        __half2 hh[4] = { __floats2half2_rn(a.x, a.y),
                          __floats2half2_rn(a.z, a.w),
                          __floats2half2_rn(b.x, b.y),
                          __floats2half2_rn(b.z, b.w) };
        *(uint4*)(g_wqkv + i) = *(const uint4*)hh;
        if (blk == 2144) {
            g_bqkv[tid] = bq[tid];
            g_bqkv[256 + tid] = bk[tid];
            g_bqkv[512 + tid] = bv[tid];
        }
    } else if (blk < 7360) {
        int rel = blk - 2240;
        const float* cW = cW1;
        __half* Wt = g_wt1;
        if (rel >= 2560) { rel -= 2560; cW = cW2; Wt = g_wt2; }
        int idx = rel * 256 + tid;
        int j = idx / (Kc * Dn);
        int k = idx - j * (Kc * Dn);
        int kk = k >> 8;
        int ic = k & 255;
        int oc = (j & 1) ? (256 + (j >> 1)) : (j >> 1);
        Wt[idx] = __float2half_rn(cW[((size_t)oc * Dn + ic) * Kc + kk]);
    } else {
        // mask normalization + per-batch 1/len (single block)
        if (tid == 0) { s_nz1 = 0; s_f3 = 0; }
        __syncthreads();
        int lnz = 0, lf = 0;
        for (int i = tid; i < Mn; i += 256) {
            unsigned char v = mraw[i];
            if ((i & 3) != 0 && v != 0) lnz++;
            if ((i & 3) == 3 && v == 0x3F) lf++;
        }
        atomicAdd(&s_nz1, lnz);
        atomicAdd(&s_f3, lf);
        __syncthreads();
        int mode = (s_f3 > 0) ? 2 : ((s_nz1 > 0) ? 0 : 1);  // 0=u8 1=i32 2=f32
        for (int i = tid; i < Mn; i += 256) {
            unsigned char m;
            if (mode == 0)      m = (mraw[i] != 0);
            else if (mode == 1) m = (((const int*)mraw)[i] != 0);
            else                m = (((const float*)mraw)[i] != 0.f);
            g_mask[i] = m;
        }
        __syncthreads();
        int b = tid >> 4, seg = tid & 15;
        int cnt = 0;
        for (int t = seg * 64; t < seg * 64 + 64; t++)
            cnt += (g_mask[b * Tn + t] == 0);
#pragma unroll
        for (int o = 1; o < 16; o <<= 1)
            cnt += __shfl_xor_sync(0xffffffffu, cnt, o);
        if (seg == 0) g_cinv[b] = 1.f / (float)cnt;
    }
}

// ---------------------------------------------------------------------------
// Conv1dGLU implicit GEMM with RESIDENT A: 132 rows (m0-2..m0+129, zero-pad)
// loaded once; mainloop streams only B (3-stage). 256 threads, 2x4 warp grid,
// 64x32 warp tiles. Taps addressed via row-shifted ldsm. GLU epilogue with
// residual read from the smem A buffer.
// ---------------------------------------------------------------------------
template <bool MASKED>
__global__ void __launch_bounds__(256)
conv_gemm(const __half* __restrict__ A, const __half* __restrict__ Bm,
          const float* __restrict__ bias, __half* __restrict__ C) {
    extern __shared__ char sm[];             // A[132 rows] then B[3 stages]
    char* smB = sm + ABUF_B;
    const unsigned smA_s = (unsigned)__cvta_generic_to_shared(sm);
    const unsigned smB_s = smA_s + ABUF_B;

    const int m0 = blockIdx.y * 128;
    const int n0 = blockIdx.x * 128;
    const int tid  = threadIdx.x;
    const int warp = tid >> 5, lane = tid & 31;
    const int wr = warp >> 2, wc = warp & 3;     // 2 x 4 warp grid
    const int gid = lane >> 2, tig = lane & 3;
    const int lr8 = lane & 7;

    // A fragment base offsets (row +2 bias for the dt=-2..2 shift window)
    unsigned aoff[4], boff[2];
#pragma unroll
    for (int mt = 0; mt < 4; mt++)
        aoff[mt] = (unsigned)((wr * 64 + mt * 16 + lr8 + ((lane >> 3) & 1) * 8
                   + 2) * AROW_B + ((lane >> 4) & 1) * 16);
#pragma unroll
    for (int np = 0; np < 2; np++)
        boff[np] = (unsigned)((wc * 32 + np * 16 + lr8 + ((lane >> 4) & 1) * 8)
                   * ROW_B + ((lane >> 3) & 1) * 16);

    // ---- load resident A (132 rows x 256 halves), zero-pad out-of-range ----
    const int t0 = m0 & (Tn - 1);
#pragma unroll
    for (int p = 0; p < 17; p++) {
        int idx = tid + p * 256;
        if (idx < 132 * 32) {
            int row = idx >> 5, ch = idx & 31;
            int t = t0 - 2 + row;
            bool ok = (unsigned)t < (unsigned)Tn;
            const __half* g = A + (size_t)(m0 + (ok ? (row - 2) : 0)) * Dn +
                              ch * 8;
            cpa16p(sm + row * AROW_B + ch * 16, g, ok);
        }
    }
    auto loadB = [&](int buf, int kt) {
#pragma unroll
        for (int p = 0; p < 2; p++) {
            int idx = tid + p * 256;
            int row = idx >> 2, ch = idx & 3;
            cpa16(smB + buf * TILE_B + row * ROW_B + ch * 16,
                  Bm + (size_t)(n0 + row) * (Kc * Dn) + kt + ch * 8);
        }
    };
    loadB(0, 0);
    asm volatile("cp.async.commit_group;" ::: "memory");   // group: A + B0
    loadB(1, 32);
    asm volatile("cp.async.commit_group;" ::: "memory");

    float acc[4][4][4];
#pragma unroll
    for (int i = 0; i < 4; i++)
#pragma unroll
        for (int j = 0; j < 4; j++)
#pragma unroll
            for (int q = 0; q < 4; q++) acc[i][j][q] = 0.f;

    const int nIter = (Kc * Dn) >> 5;            // 40
    for (int it = 0; it < nIter; it++) {
        int buf = it % 3;
        if (it + 1 < nIter) {
            asm volatile("cp.async.wait_group 1;" ::: "memory");
        } else {
            asm volatile("cp.async.wait_group 0;" ::: "memory");
        }
        __syncthreads();
        if (it + 2 < nIter) {
            loadB((it + 2) % 3, (it + 2) << 5);
            asm volatile("cp.async.commit_group;" ::: "memory");
        }

        // tap shift and input-channel byte offset for this k-block
        const int adl = ((it >> 3) - 2) * AROW_B + (it & 7) * 64;
        const unsigned baseB = smB_s + buf * TILE_B;
#pragma unroll
        for (int ks = 0; ks < 2; ks++) {
            unsigned kb = ks * 32;
            unsigned af[4][4];
#pragma unroll
            for (int mt = 0; mt < 4; mt++)
                ldsm4(af[mt], smA_s + aoff[mt] + adl + kb);
            unsigned bfr[4][2];
#pragma unroll
            for (int np = 0; np < 2; np++) {
                unsigned bt[4];
                ldsm4(bt, baseB + kb + boff[np]);
                bfr[2 * np][0] = bt[0]; bfr[2 * np][1] = bt[1];
                bfr[2 * np + 1][0] = bt[2]; bfr[2 * np + 1][1] = bt[3];
            }
#pragma unroll
            for (int mt = 0; mt < 4; mt++)
#pragma unroll
                for (int nt = 0; nt < 4; nt++)
                    mma_f16(acc[mt][nt], af[mt], bfr[nt]);
        }
    }

    // ---- GLU epilogue (residual from smem A): even n = a, odd n = gate ----
    const __half* Asm = (const __half*)sm;
#pragma unroll
    for (int mt = 0; mt < 4; mt++) {
#pragma unroll
        for (int nt = 0; nt < 4; nt++) {
            int n = n0 + wc * 32 + nt * 8 + 2 * tig;
            int i = n >> 1;
#pragma unroll
            for (int half_ = 0; half_ < 2; half_++) {
                int mr = wr * 64 + mt * 16 + gid + half_ * 8;  // 0..127
                int m = m0 + mr;
                float a = acc[mt][nt][half_ * 2 + 0] + bias[i];
                float g = acc[mt][nt][half_ * 2 + 1] + bias[256 + i];
                float v = __half2float(Asm[(mr + 2) * 264 + i]) +
                          a * sigmoidf(g);
                if (MASKED && g_mask[m]) v = 0.f;
                C[(size_t)m * 256 + i] = __float2half_rn(v);
            }
        }
    }
}

// ---------------------------------------------------------------------------
// FP16 tensor-core TN GEMM: C = epi( A[M,K](lda) @ B[N,K](ldb)^T )
// 128x128 tile, BK=32, 256 threads, 4-stage cp.async (1 barrier/iter).
// EPI: 1=mish(+bias) half,
//      8=QKV fused (n<512 -> qk, n>=512 -> vt transpose; res=vt out),
//      9=Wo: +bias+res, masked pool directly into g_Sp (no C store)
// ---------------------------------------------------------------------------
template <int EPI>
__global__ void __launch_bounds__(256)
mma_gemm(const __half* __restrict__ A, const __half* __restrict__ Bm,
         const float* __restrict__ bias, const __half* __restrict__ res,
         void* __restrict__ Cv, int K, int lda, int ldb, int ldc) {
    extern __shared__ char sm[];             // A[4] then B[4]
    char* smB = sm + STAGES * TILE_B;
    const unsigned smA_s = (unsigned)__cvta_generic_to_shared(sm);
    const unsigned smB_s = smA_s + STAGES * TILE_B;

    const int m0 = blockIdx.y * 128;
    const int n0 = blockIdx.x * 128;
    const int tid  = threadIdx.x;
    const int warp = tid >> 5, lane = tid & 31;
    const int wr = warp >> 2, wc = warp & 3;     // 2 x 4 warp grid
    const int gid = lane >> 2, tig = lane & 3;

    const int lr8 = lane & 7;
    unsigned aoff[4], boff[2];
#pragma unroll
    for (int mt = 0; mt < 4; mt++)
        aoff[mt] = (unsigned)((wr * 64 + mt * 16 + lr8 + ((lane >> 3) & 1) * 8)
                   * ROW_B + ((lane >> 4) & 1) * 16);
#pragma unroll
    for (int np = 0; np < 2; np++)
        boff[np] = (unsigned)((wc * 32 + np * 16 + lr8 + ((lane >> 4) & 1) * 8)
                   * ROW_B + ((lane >> 3) & 1) * 16);

    auto load_tiles = [&](int buf, int kt) {
#pragma unroll
        for (int p = 0; p < 2; p++) {
            int idx = tid + p * 256;
            int row = idx >> 2, ch = idx & 3;
            cpa16(sm + buf * TILE_B + row * ROW_B + ch * 16,
                  A + (size_t)(m0 + row) * lda + kt + ch * 8);
            cpa16(smB + buf * TILE_B + row * ROW_B + ch * 16,
                  Bm + (size_t)(n0 + row) * ldb + kt + ch * 8);
        }
    };

    float acc[4][4][4];
#pragma unroll
    for (int i = 0; i < 4; i++)
#pragma unroll
        for (int j = 0; j < 4; j++)
#pragma unroll
            for (int q = 0; q < 4; q++) acc[i][j][q] = 0.f;

    const int nIter = K >> 5;                    // BK = 32 halves, nIter >= 4
    load_tiles(0, 0);
    asm volatile("cp.async.commit_group;" ::: "memory");
    load_tiles(1, 32);
    asm volatile("cp.async.commit_group;" ::: "memory");
    load_tiles(2, 64);
    asm volatile("cp.async.commit_group;" ::: "memory");

    for (int it = 0; it < nIter; it++) {
        int buf = it & 3;
        if (it + 2 < nIter) {
            asm volatile("cp.async.wait_group 2;" ::: "memory");
        } else if (it + 1 < nIter) {
            asm volatile("cp.async.wait_group 1;" ::: "memory");
        } else {
            asm volatile("cp.async.wait_group 0;" ::: "memory");
        }
        __syncthreads();
        if (it + 3 < nIter) {
            load_tiles((it + 3) & 3, (it + 3) << 5);
            asm volatile("cp.async.commit_group;" ::: "memory");
        }

        const unsigned baseA = smA_s + buf * TILE_B;
        const unsigned baseB = smB_s + buf * TILE_B;
#pragma unroll
        for (int ks = 0; ks < 2; ks++) {
            unsigned kb = ks * 32;
            unsigned af[4][4];
#pragma unroll
            for (int mt = 0; mt < 4; mt++)
                ldsm4(af[mt], baseA + kb + aoff[mt]);
            unsigned bfr[4][2];
#pragma unroll
            for (int np = 0; np < 2; np++) {
                unsigned bt[4];
                ldsm4(bt, baseB + kb + boff[np]);
                bfr[2 * np][0] = bt[0]; bfr[2 * np][1] = bt[1];
                bfr[2 * np + 1][0] = bt[2]; bfr[2 * np + 1][1] = bt[3];
            }
#pragma unroll
            for (int mt = 0; mt < 4; mt++)
#pragma unroll
                for (int nt = 0; nt < 4; nt++)
                    mma_f16(acc[mt][nt], af[mt], bfr[nt]);
        }
    }

    // ---- epilogue ----
    if (EPI == 9) {
        float ls[4][2];
#pragma unroll
        for (int nt = 0; nt < 4; nt++) { ls[nt][0] = 0.f; ls[nt][1] = 0.f; }
#pragma unroll
        for (int mt = 0; mt < 4; mt++)
#pragma unroll
            for (int half_ = 0; half_ < 2; half_++) {
                int m = m0 + wr * 64 + mt * 16 + gid + half_ * 8;
                bool keep = (g_mask[m] == 0);
#pragma unroll
                for (int nt = 0; nt < 4; nt++) {
                    int n = n0 + wc * 32 + nt * 8 + 2 * tig;
                    float v0 = acc[mt][nt][half_ * 2 + 0] + bias[n] +
                               __half2float(res[(size_t)m * ldc + n]);
                    float v1 = acc[mt][nt][half_ * 2 + 1] + bias[n + 1] +
                               __half2float(res[(size_t)m * ldc + n + 1]);
                    if (keep) { ls[nt][0] += v0; ls[nt][1] += v1; }
                }
            }
#pragma unroll
        for (int nt = 0; nt < 4; nt++)
#pragma unroll
            for (int c = 0; c < 2; c++) {
                float r = ls[nt][c];
                r += __shfl_xor_sync(0xffffffffu, r, 4);
                r += __shfl_xor_sync(0xffffffffu, r, 8);
                r += __shfl_xor_sync(0xffffffffu, r, 16);
                ls[nt][c] = r;
            }
        __syncthreads();
        float* spf = (float*)sm;
        if (lane < 4) {
#pragma unroll
            for (int nt = 0; nt < 4; nt++) {
                spf[warp * 32 + lane * 8 + nt * 2 + 0] = ls[nt][0];
                spf[warp * 32 + lane * 8 + nt * 2 + 1] = ls[nt][1];
            }
        }
        __syncthreads();
        if (warp < 4) {
            float s = spf[warp * 32 + lane] + spf[(warp + 4) * 32 + lane];
            int tig_ = lane >> 3, nt_ = (lane >> 1) & 3, c_ = lane & 1;
            int n = n0 + warp * 32 + nt_ * 8 + 2 * tig_ + c_;
            int y = m0 >> 7, b = y >> 3, chunk = y & 7;
            g_Sp[chunk][b * Dn + n] = s;
        }
        return;
    }

#pragma unroll
    for (int mt = 0; mt < 4; mt++) {
#pragma unroll
        for (int nt = 0; nt < 4; nt++) {
            int mbase = m0 + wr * 64 + mt * 16 + gid;
            int n = n0 + wc * 32 + nt * 8 + 2 * tig;
#pragma unroll
            for (int half_ = 0; half_ < 2; half_++) {
                int m = mbase + half_ * 8;
                float v0 = acc[mt][nt][half_ * 2 + 0];
                float v1 = acc[mt][nt][half_ * 2 + 1];
                if (EPI == 8) {
                    v0 += bias[n]; v1 += bias[n + 1];
                    if (n0 < 512) {              // q,k region
                        __half* C = (__half*)Cv;
                        *(__half2*)(C + (size_t)m * 512 + n) =
                            __floats2half2_rn(v0, v1);
                    } else {                     // v region -> transposed store
                        __half* VT = (__half*)(void*)res;
                        int bb = m >> 10, t = m & (Tn - 1);
                        int d = n - 512;
                        VT[((size_t)((bb * 2 + (d >> 7)) * 128 + (d & 127))) * Tn + t] =
                            __float2half_rn(v0);
                        d = n + 1 - 512;
                        VT[((size_t)((bb * 2 + (d >> 7)) * 128 + (d & 127))) * Tn + t] =
                            __float2half_rn(v1);
                    }
                } else {                          // EPI == 1 (mish)
                    __half* C = (__half*)Cv;
                    v0 = mishf(v0 + bias[n]);
                    v1 = mishf(v1 + bias[n + 1]);
                    *(__half2*)(C + (size_t)m * ldc + n) =
                        __floats2half2_rn(v0, v1);
                }
            }
        }
    }
}

// ---------------------------------------------------------------------------
// Fused attention (no-max flash). Grid (8 q-tiles, 32 bh), 256 threads.
// ---------------------------------------------------------------------------
__global__ void __launch_bounds__(256)
flash_kernel(const __half* __restrict__ qk, const __half* __restrict__ vt,
             __half* __restrict__ attn) {
    const int qt = blockIdx.x;
    const int z  = blockIdx.y;
    const int zb = z >> 1, zh = z & 1;
    extern __shared__ char sm[];
    const unsigned smQ = (unsigned)__cvta_generic_to_shared(sm);
    const int tid = threadIdx.x, warp = tid >> 5, lane = tid & 31;
    const int gid = lane >> 2, tig = lane & 3, lr8 = lane & 7;

    const unsigned aoffQ = (unsigned)((warp * 16 + lr8 + ((lane >> 3) & 1) * 8)
                           * FROW_B + ((lane >> 4) & 1) * 16);
    unsigned boffF[8];
#pragma unroll
    for (int np = 0; np < 8; np++)
        boffF[np] = (unsigned)((np * 16 + lr8 + ((lane >> 4) & 1) * 8)
                    * FROW_B + ((lane >> 3) & 1) * 16);

    auto loadQ = [&]() {
#pragma unroll
        for (int p = 0; p < 8; p++) {
            int idx = tid + p * 256;
            int row = idx >> 4, ch = idx & 15;
            cpa16(sm + row * FROW_B + ch * 16,
                  qk + (size_t)(zb * Tn + qt * 128 + row) * 512 +
                  zh * 128 + ch * 8);
        }
    };
    auto loadK = [&](int buf, int jt) {
#pragma unroll
        for (int p = 0; p < 8; p++) {
            int idx = tid + p * 256;
            int row = idx >> 4, ch = idx & 15;
            cpa16(sm + FK_OFF + buf * FTILE_B + row * FROW_B + ch * 16,
                  qk + (size_t)(zb * Tn + jt * 128 + row) * 512 +
                  256 + zh * 128 + ch * 8);
        }
    };
    auto loadV = [&](int buf, int jt) {
#pragma unroll
        for (int p = 0; p < 8; p++) {
            int idx = tid + p * 256;
            int row = idx >> 4, ch = idx & 15;
            cpa16(sm + FV_OFF + buf * FTILE_B + row * FROW_B + ch * 16,
                  vt + (size_t)(z * 128 + row) * Tn + jt * 128 + ch * 8);
        }
    };

    loadQ(); loadK(0, 0); loadV(0, 0);
    asm volatile("cp.async.commit_group;" ::: "memory");

    float O[16][4];
#pragma unroll
    for (int i = 0; i < 16; i++)
#pragma unroll
        for (int q = 0; q < 4; q++) O[i][q] = 0.f;
    float rs0 = 0.f, rs1 = 0.f;
    unsigned qf[8][4];

    for (int jt = 0; jt < 8; jt++) {
        int buf = jt & 1;
        asm volatile("cp.async.wait_group 0;" ::: "memory");
        __syncthreads();
        if (jt < 7) {
            loadK(buf ^ 1, jt + 1);
            loadV(buf ^ 1, jt + 1);
            asm volatile("cp.async.commit_group;" ::: "memory");
        }
        if (jt == 0) {
#pragma unroll
            for (int kd = 0; kd < 8; kd++)
                ldsm4(qf[kd], smQ + kd * 32 + aoffQ);
        }

        float S[16][4];
#pragma unroll
        for (int i = 0; i < 16; i++)
#pragma unroll
            for (int q = 0; q < 4; q++) S[i][q] = 0.f;
        const unsigned baseK = smQ + FK_OFF + buf * FTILE_B;
#pragma unroll
        for (int kd = 0; kd < 8; kd++) {
#pragma unroll
            for (int np = 0; np < 8; np++) {
                unsigned bt[4];
                ldsm4(bt, baseK + kd * 32 + boffF[np]);
                mma_f16(S[2 * np],     qf[kd], bt);
                mma_f16(S[2 * np + 1], qf[kd], bt + 2);
            }
        }

        unsigned P[16][2];
        const unsigned char* mkb = g_mask + zb * Tn + jt * 128;
#pragma unroll
        for (int nt = 0; nt < 16; nt++) {
            int c0 = nt * 8 + 2 * tig;
            bool mA = mkb[c0], mB = mkb[c0 + 1];
            float e0 = mA ? 0.f : __expf(fminf(S[nt][0] * SCALE_ATTN, 15.f));
            float e1 = mB ? 0.f : __expf(fminf(S[nt][1] * SCALE_ATTN, 15.f));
            float e2 = mA ? 0.f : __expf(fminf(S[nt][2] * SCALE_ATTN, 15.f));
            float e3 = mB ? 0.f : __expf(fminf(S[nt][3] * SCALE_ATTN, 15.f));
            rs0 += e0 + e1;
            rs1 += e2 + e3;
            P[nt][0] = pack2(e0, e1);
            P[nt][1] = pack2(e2, e3);
        }

        const unsigned baseV = smQ + FV_OFF + buf * FTILE_B;
#pragma unroll
        for (int s = 0; s < 8; s++) {
            unsigned a2[4] = { P[2 * s][0], P[2 * s][1],
                               P[2 * s + 1][0], P[2 * s + 1][1] };
#pragma unroll
            for (int np = 0; np < 8; np++) {
                unsigned bt[4];
                ldsm4(bt, baseV + s * 32 + boffF[np]);
                mma_f16(O[2 * np],     a2, bt);
                mma_f16(O[2 * np + 1], a2, bt + 2);
            }
        }
    }

    // quad-reduce row sums (each lane holds 2 of every 8 columns)
    rs0 += __shfl_xor_sync(0xffffffffu, rs0, 1);
    rs0 += __shfl_xor_sync(0xffffffffu, rs0, 2);
    rs1 += __shfl_xor_sync(0xffffffffu, rs1, 1);
    rs1 += __shfl_xor_sync(0xffffffffu, rs1, 2);

    float i0 = 1.f / rs0, i1 = 1.f / rs1;
    int t = qt * 128 + warp * 16 + gid;
    __half* dst = attn + (size_t)(zb * Tn + t) * 256 + zh * 128;
#pragma unroll
    for (int nt = 0; nt < 16; nt++) {
        int d = nt * 8 + 2 * tig;
        *(__half2*)(dst + d) = __floats2half2_rn(O[nt][0] * i0, O[nt][1] * i0);
        *(__half2*)(dst + (size_t)8 * 256 + d) =
            __floats2half2_rn(O[nt][2] * i1, O[nt][3] * i1);
    }
}

// out[b,n] = (S_b @ Wf^T)[n]/len_b + bf[n]
__global__ void final_kernel(const float* __restrict__ Wf,
                             const float* __restrict__ bf,
                             float* __restrict__ out) {
    int b = blockIdx.x;
    int n = threadIdx.x;
    __shared__ float sb[Dn];
    float s = 0.f;
#pragma unroll
    for (int c = 0; c < 8; c++) s += g_Sp[c][b * Dn + n];
    sb[n] = s;
    __syncthreads();
    float acc = 0.f;
    const float* w = Wf + (size_t)n * Dn;
#pragma unroll 8
    for (int k = 0; k < Dn; k++) acc = fmaf(sb[k], w[k], acc);
    out[b * Dn + n] = acc * g_cinv[b] + bf[n];
}

// ---------------------------------------------------------------------------
extern "C" void kernel_launch(void* const* d_in, const int* in_sizes, int n_in,
                              void* d_out, int out_size) {
    (void)in_sizes; (void)n_in; (void)out_size;
    const float* x   = (const float*)d_in[0];
    const unsigned char* mraw = (const unsigned char*)d_in[1];
    const float* W1  = (const float*)d_in[2];
    const float* b1  = (const float*)d_in[3];
    const float* W2  = (const float*)d_in[4];
    const float* b2  = (const float*)d_in[5];
    const float* cW1 = (const float*)d_in[6];
    const float* cb1 = (const float*)d_in[7];
    const float* cW2 = (const float*)d_in[8];
    const float* cb2 = (const float*)d_in[9];
    const float* Wq  = (const float*)d_in[10];
    const float* bq  = (const float*)d_in[11];
    const float* Wk  = (const float*)d_in[12];
    const float* bk  = (const float*)d_in[13];
    const float* Wv  = (const float*)d_in[14];
    const float* bv  = (const float*)d_in[15];
    const float* Wo  = (const float*)d_in[16];
    const float* bo  = (const float*)d_in[17];
    const float* Wf  = (const float*)d_in[18];
    const float* bf  = (const float*)d_in[19];
    float* out = (float*)d_out;

    __half *xh, *h1, *h2, *h3, *res, *qk, *vt, *attn;
    __half *wt1, *wt2, *w1h, *w2h, *woh, *wqkv;
    float *bqkv;
    cudaGetSymbolAddress((void**)&xh, g_xh);
    cudaGetSymbolAddress((void**)&h1, g_h1);
    cudaGetSymbolAddress((void**)&h2, g_h2);
    cudaGetSymbolAddress((void**)&h3, g_h3);
    cudaGetSymbolAddress((void**)&res, g_res);
    cudaGetSymbolAddress((void**)&qk, g_qk);
    cudaGetSymbolAddress((void**)&vt, g_vt);
    cudaGetSymbolAddress((void**)&attn, g_attn);
    cudaGetSymbolAddress((void**)&wt1, g_wt1);
    cudaGetSymbolAddress((void**)&wt2, g_wt2);
    cudaGetSymbolAddress((void**)&w1h, g_w1h);
    cudaGetSymbolAddress((void**)&w2h, g_w2h);
    cudaGetSymbolAddress((void**)&woh, g_woh);
    cudaGetSymbolAddress((void**)&wqkv, g_wqkv);
    cudaGetSymbolAddress((void**)&bqkv, g_bqkv);

    cudaFuncSetAttribute(mma_gemm<1>, cudaFuncAttributeMaxDynamicSharedMemorySize, SMEM_SZ);
    cudaFuncSetAttribute(mma_gemm<8>, cudaFuncAttributeMaxDynamicSharedMemorySize, SMEM_SZ);
    cudaFuncSetAttribute(mma_gemm<9>, cudaFuncAttributeMaxDynamicSharedMemorySize, SMEM_SZ);
    cudaFuncSetAttribute(conv_gemm<false>, cudaFuncAttributeMaxDynamicSharedMemorySize, CSMEM);
    cudaFuncSetAttribute(conv_gemm<true>,  cudaFuncAttributeMaxDynamicSharedMemorySize, CSMEM);
    cudaFuncSetAttribute(flash_kernel, cudaFuncAttributeMaxDynamicSharedMemorySize, FSMEM);

    // 0) single merged prep pass (incl. mask normalization block)
    prep_all<<<7361, 256>>>(x, W1, W2, Wo, Wq, Wk, Wv, bq, bk, bv,
                            cW1, cW2, mraw);

    dim3 gDense(2, 128, 1);
    dim3 gConv(4, 128, 1);
    dim3 gQKV(6, 128, 1);
    dim3 gFlash(8, 32, 1);

    // 1) spectral MLP (Linear + Mish) x2
    mma_gemm<1><<<gDense, 256, SMEM_SZ>>>(xh, w1h, b1, nullptr, h1,
        Dn, Dn, Dn, Dn);
    mma_gemm<1><<<gDense, 256, SMEM_SZ>>>(h1, w2h, b2, nullptr, h2,
        Dn, Dn, Dn, Dn);

    // 2) Conv1dGLU x2 (resident-A conv kernel, GLU fused, residual from smem)
    conv_gemm<false><<<gConv, 256, CSMEM>>>(h2, wt1, cb1, h3);
    conv_gemm<true><<<gConv, 256, CSMEM>>>(h3, wt2, cb2, res);

    // 3) fused q,k,v projection (N=768; v written transposed via res ptr)
    mma_gemm<8><<<gQKV, 256, SMEM_SZ>>>(res, wqkv, bqkv, vt, qk,
        Dn, Dn, Dn, 512);

    // 4) fused attention (flash, no-max)
    flash_kernel<<<gFlash, 256, FSMEM>>>(qk, vt, attn);

    // 5) output projection + residual with fused masked pool (no h5 store)
    mma_gemm<9><<<gDense, 256, SMEM_SZ>>>(attn, woh, bo, res, nullptr,
        Dn, Dn, Dn, Dn);

    // 6) tiny final GEMM (Wf applied to pooled sums)
    final_kernel<<<Bn, Dn>>>(Wf, bf, out);
}

// round 17
// speedup vs baseline: 1.1178x; 1.0422x over previous
#include <cuda_runtime.h>
#include <cuda_fp16.h>
#include <math.h>

// ---------------------------------------------------------------------------
// StylePredictor forward: B=16, T=1024, D=256, H=2, DK=128, convK=5
// FP16 tensor-core GEMMs (mma.sync.m16n8k16, fp32 accumulate), cp.async
// pipelines, BK=32, ldmatrix fragment loads. Conv keeps A resident in smem.
// Flash attention: exp via ex2.approx.f16x2, mask multiplicative (smem half),
// row sums via an appended all-ones V column (fp32, from the PV matmul).
// ---------------------------------------------------------------------------

constexpr int Bn  = 16;
constexpr int Tn  = 1024;
constexpr int Dn  = 256;
constexpr int Hn  = 2;
constexpr int Kc  = 5;
constexpr int Mn  = Bn * Tn;                 // 16384 rows
constexpr float SCALE_ATTN = 1.0f / 16.0f;   // 1/sqrt(256)
constexpr float CL2E = 0.0901688f;           // SCALE_ATTN * log2(e)

constexpr int ROW_B   = 80;                  // GEMM smem row stride (bytes)
constexpr int TILE_B  = 128 * ROW_B;         // 10240
constexpr int STAGES  = 4;
constexpr int SMEM_SZ = 2 * STAGES * TILE_B; // 81920 -> 2 CTA/SM

// conv: resident A buffer (132 rows x 256 halves, 528B stride) + 3 B stages
constexpr int AROW_B  = 528;
constexpr int ABUF_B  = 132 * AROW_B;        // 69696
constexpr int CSMEM   = ABUF_B + 3 * TILE_B; // 100416 -> 2 CTA/SM

// flash tiles: 128 rows x 128 halves (256B) padded to 272B; V has 144 rows
// (row 128 = ones column for rowsum, 129-143 zero pad for ldsm)
constexpr int FROW_B   = 272;
constexpr int FTILE_B  = 128 * FROW_B;       // 34816
constexpr int FVTILE_B = 144 * FROW_B;       // 39168
constexpr int FK_OFF   = FTILE_B;            // K double buffer
constexpr int FV_OFF   = 3 * FTILE_B;        // V double buffer (144-row tiles)
constexpr int MASK_OFF = FV_OFF + 2 * FVTILE_B;  // 182784
constexpr int FSMEM    = MASK_OFF + 2048;    // 184832 -> 1 CTA/SM

__device__ __half g_xh[Mn * Dn];
__device__ __half g_h1[Mn * Dn];
__device__ __half g_h2[Mn * Dn];
__device__ __half g_h3[Mn * Dn];
__device__ __half g_res[Mn * Dn];
__device__ __half g_qk[Mn * 2 * Dn];
__device__ __half g_vt[Mn * Dn];             // [bh][128 d][1024 t]
__device__ __half g_attn[Mn * Dn];
__device__ __half g_wt1[2 * Dn * Kc * Dn];   // [512 j][1280 k] interleaved a/g
__device__ __half g_wt2[2 * Dn * Kc * Dn];
__device__ __half g_w1h[Dn * Dn];
__device__ __half g_w2h[Dn * Dn];
__device__ __half g_woh[Dn * Dn];
__device__ __half g_wqkv[3 * Dn * Dn];       // rows: q 0..255, k 256..511, v 512..767
__device__ float  g_bqkv[3 * Dn];
__device__ float  g_Sp[8][Bn * Dn];
__device__ float  g_cinv[Bn];
__device__ unsigned char g_mask[Mn];
__device__ __half g_maskh[Mn];               // 1.0 = keep, 0.0 = masked

// mish(x) = x * tanh(softplus(x)) = x * (t^2 + 2t) / (t^2 + 2t + 2), t = e^x
__device__ __forceinline__ float mishf(float x) {
    if (x > 20.f) return x;
    float t = __expf(x);
    float u = t * t + 2.f * t;
    return x * __fdividef(u, u + 2.f);
}
__device__ __forceinline__ float sigmoidf(float x) {
    return 1.f / (1.f + __expf(-x));
}
__device__ __forceinline__ unsigned ex2h2(unsigned x) {
    unsigned d;
    asm("ex2.approx.f16x2 %0, %1;" : "=r"(d) : "r"(x));
    return d;
}
__device__ __forceinline__ void mma_f16(float* c, const unsigned* a,
                                        const unsigned* b) {
    asm volatile(
        "mma.sync.aligned.m16n8k16.row.col.f32.f16.f16.f32 "
        "{%0,%1,%2,%3}, {%4,%5,%6,%7}, {%8,%9}, {%0,%1,%2,%3};"
        : "+f"(c[0]), "+f"(c[1]), "+f"(c[2]), "+f"(c[3])
        : "r"(a[0]), "r"(a[1]), "r"(a[2]), "r"(a[3]), "r"(b[0]), "r"(b[1]));
}
__device__ __forceinline__ void ldsm4(unsigned* r, unsigned saddr) {
    asm volatile(
        "ldmatrix.sync.aligned.m8n8.x4.shared.b16 {%0,%1,%2,%3}, [%4];"
        : "=r"(r[0]), "=r"(r[1]), "=r"(r[2]), "=r"(r[3]) : "r"(saddr));
}
__device__ __forceinline__ void cpa16(void* dst, const void* g) {
    unsigned s = (unsigned)__cvta_generic_to_shared(dst);
    asm volatile("cp.async.ca.shared.global [%0], [%1], 16;"
                 :: "r"(s), "l"(g) : "memory");
}
__device__ __forceinline__ void cpa16p(void* dst, const void* g, bool ok) {
    unsigned s = (unsigned)__cvta_generic_to_shared(dst);
    int sz = ok ? 16 : 0;
    asm volatile("cp.async.ca.shared.global [%0], [%1], 16, %2;"
                 :: "r"(s), "l"(g), "r"(sz) : "memory");
}

// ---------------------------------------------------------------------------
// Merged prep: fp32->fp16 conversions + weight packing + mask normalization
// (block 7360) in ONE launch.
// ---------------------------------------------------------------------------
__device__ __forceinline__ void cvt8(const float* __restrict__ src,
                                     __half* __restrict__ dst, int i) {
    float4 a = *(const float4*)(src + i);
    float4 b = *(const float4*)(src + i + 4);
    __half2 hh[4] = { __floats2half2_rn(a.x, a.y), __floats2half2_rn(a.z, a.w),
                      __floats2half2_rn(b.x, b.y), __floats2half2_rn(b.z, b.w) };
    *(uint4*)(dst + i) = *(const uint4*)hh;
}

__global__ void prep_all(const float* __restrict__ x,
                         const float* __restrict__ W1,
                         const float* __restrict__ W2,
                         const float* __restrict__ Wo,
                         const float* __restrict__ Wq,
                         const float* __restrict__ Wk,
                         const float* __restrict__ Wv,
                         const float* __restrict__ bq,
                         const float* __restrict__ bk,
                         const float* __restrict__ bv,
                         const float* __restrict__ cW1,
                         const float* __restrict__ cW2,
                         const unsigned char* __restrict__ mraw) {
    __shared__ int s_nz1, s_f3;
    int blk = blockIdx.x, tid = threadIdx.x;
    if (blk < 2144) {
        const float* src;
        __half* dst;
        int base;
        if (blk < 2048)      { src = x;  dst = g_xh;  base = blk; }
        else if (blk < 2080) { src = W1; dst = g_w1h; base = blk - 2048; }
        else if (blk < 2112) { src = W2; dst = g_w2h; base = blk - 2080; }
        else                 { src = Wo; dst = g_woh; base = blk - 2112; }
        cvt8(src, dst, (base * 256 + tid) * 8);
    } else if (blk < 2240) {
        int i = ((blk - 2144) * 256 + tid) * 8;          // 0..196607
        int which = i >> 16;
        const float* src = (which == 0) ? Wq : (which == 1 ? Wk : Wv);
        int j = i & 65535;
        float4 a = *(const float4*)(src + j);
        float4 b = *(const float4*)(src + j + 4);
        __half2 hh[4] = { __floats2half2_rn(a.x, a.y),
                          __floats2half2_rn(a.z, a.w),
                          __floats2half2_rn(b.x, b.y),
                          __floats2half2_rn(b.z, b.w) };
        *(uint4*)(g_wqkv + i) = *(const uint4*)hh;
        if (blk == 2144) {
            g_bqkv[tid] = bq[tid];
            g_bqkv[256 + tid] = bk[tid];
            g_bqkv[512 + tid] = bv[tid];
        }
    } else if (blk < 7360) {
        int rel = blk - 2240;
        const float* cW = cW1;
        __half* Wt = g_wt1;
        if (rel >= 2560) { rel -= 2560; cW = cW2; Wt = g_wt2; }
        int idx = rel * 256 + tid;
        int j = idx / (Kc * Dn);
        int k = idx - j * (Kc * Dn);
        int kk = k >> 8;
        int ic = k & 255;
        int oc = (j & 1) ? (256 + (j >> 1)) : (j >> 1);
        Wt[idx] = __float2half_rn(cW[((size_t)oc * Dn + ic) * Kc + kk]);
    } else {
        // mask normalization + per-batch 1/len (single block)
        if (tid == 0) { s_nz1 = 0; s_f3 = 0; }
        __syncthreads();
        int lnz = 0, lf = 0;
        for (int i = tid; i < Mn; i += 256) {
            unsigned char v = mraw[i];
            if ((i & 3) != 0 && v != 0) lnz++;
            if ((i & 3) == 3 && v == 0x3F) lf++;
        }
        atomicAdd(&s_nz1, lnz);
        atomicAdd(&s_f3, lf);
        __syncthreads();
        int mode = (s_f3 > 0) ? 2 : ((s_nz1 > 0) ? 0 : 1);  // 0=u8 1=i32 2=f32
        for (int i = tid; i < Mn; i += 256) {
            unsigned char m;
            if (mode == 0)      m = (mraw[i] != 0);
            else if (mode == 1) m = (((const int*)mraw)[i] != 0);
            else                m = (((const float*)mraw)[i] != 0.f);
            g_mask[i] = m;
            g_maskh[i] = __float2half(m ? 0.f : 1.f);
        }
        __syncthreads();
        int b = tid >> 4, seg = tid & 15;
        int cnt = 0;
        for (int t = seg * 64; t < seg * 64 + 64; t++)
            cnt += (g_mask[b * Tn + t] == 0);
#pragma unroll
        for (int o = 1; o < 16; o <<= 1)
            cnt += __shfl_xor_sync(0xffffffffu, cnt, o);
        if (seg == 0) g_cinv[b] = 1.f / (float)cnt;
    }
}

// ---------------------------------------------------------------------------
// Conv1dGLU implicit GEMM with RESIDENT A: 132 rows (m0-2..m0+129, zero-pad)
// loaded once; mainloop streams only B (3-stage). 256 threads, 2x4 warp grid,
// 64x32 warp tiles. GLU epilogue with residual read from the smem A buffer.
// ---------------------------------------------------------------------------
template <bool MASKED>
__global__ void __launch_bounds__(256)
conv_gemm(const __half* __restrict__ A, const __half* __restrict__ Bm,
          const float* __restrict__ bias, __half* __restrict__ C) {
    extern __shared__ char sm[];             // A[132 rows] then B[3 stages]
    char* smB = sm + ABUF_B;
    const unsigned smA_s = (unsigned)__cvta_generic_to_shared(sm);
    const unsigned smB_s = smA_s + ABUF_B;

    const int m0 = blockIdx.y * 128;
    const int n0 = blockIdx.x * 128;
    const int tid  = threadIdx.x;
    const int warp = tid >> 5, lane = tid & 31;
    const int wr = warp >> 2, wc = warp & 3;     // 2 x 4 warp grid
    const int gid = lane >> 2, tig = lane & 3;
    const int lr8 = lane & 7;

    unsigned aoff[4], boff[2];
#pragma unroll
    for (int mt = 0; mt < 4; mt++)
        aoff[mt] = (unsigned)((wr * 64 + mt * 16 + lr8 + ((lane >> 3) & 1) * 8
                   + 2) * AROW_B + ((lane >> 4) & 1) * 16);
#pragma unroll
    for (int np = 0; np < 2; np++)
        boff[np] = (unsigned)((wc * 32 + np * 16 + lr8 + ((lane >> 4) & 1) * 8)
                   * ROW_B + ((lane >> 3) & 1) * 16);

    // ---- load resident A (132 rows x 256 halves), zero-pad out-of-range ----
    const int t0 = m0 & (Tn - 1);
#pragma unroll
    for (int p = 0; p < 17; p++) {
        int idx = tid + p * 256;
        if (idx < 132 * 32) {
            int row = idx >> 5, ch = idx & 31;
            int t = t0 - 2 + row;
            bool ok = (unsigned)t < (unsigned)Tn;
            const __half* g = A + (size_t)(m0 + (ok ? (row - 2) : 0)) * Dn +
                              ch * 8;
            cpa16p(sm + row * AROW_B + ch * 16, g, ok);
        }
    }
    auto loadB = [&](int buf, int kt) {
#pragma unroll
        for (int p = 0; p < 2; p++) {
            int idx = tid + p * 256;
            int row = idx >> 2, ch = idx & 3;
            cpa16(smB + buf * TILE_B + row * ROW_B + ch * 16,
                  Bm + (size_t)(n0 + row) * (Kc * Dn) + kt + ch * 8);
        }
    };
    loadB(0, 0);
    asm volatile("cp.async.commit_group;" ::: "memory");   // group: A + B0
    loadB(1, 32);
    asm volatile("cp.async.commit_group;" ::: "memory");

    float acc[4][4][4];
#pragma unroll
    for (int i = 0; i < 4; i++)
#pragma unroll
        for (int j = 0; j < 4; j++)
#pragma unroll
            for (int q = 0; q < 4; q++) acc[i][j][q] = 0.f;

    const int nIter = (Kc * Dn) >> 5;            // 40
    for (int it = 0; it < nIter; it++) {
        int buf = it % 3;
        if (it + 1 < nIter) {
            asm volatile("cp.async.wait_group 1;" ::: "memory");
        } else {
            asm volatile("cp.async.wait_group 0;" ::: "memory");
        }
        __syncthreads();
        if (it + 2 < nIter) {
            loadB((it + 2) % 3, (it + 2) << 5);
            asm volatile("cp.async.commit_group;" ::: "memory");
        }

        const int adl = ((it >> 3) - 2) * AROW_B + (it & 7) * 64;
        const unsigned baseB = smB_s + buf * TILE_B;
#pragma unroll
        for (int ks = 0; ks < 2; ks++) {
            unsigned kb = ks * 32;
            unsigned af[4][4];
#pragma unroll
            for (int mt = 0; mt < 4; mt++)
                ldsm4(af[mt], smA_s + aoff[mt] + adl + kb);
            unsigned bfr[4][2];
#pragma unroll
            for (int np = 0; np < 2; np++) {
                unsigned bt[4];
                ldsm4(bt, baseB + kb + boff[np]);
                bfr[2 * np][0] = bt[0]; bfr[2 * np][1] = bt[1];
                bfr[2 * np + 1][0] = bt[2]; bfr[2 * np + 1][1] = bt[3];
            }
#pragma unroll
            for (int mt = 0; mt < 4; mt++)
#pragma unroll
                for (int nt = 0; nt < 4; nt++)
                    mma_f16(acc[mt][nt], af[mt], bfr[nt]);
        }
    }

    // ---- GLU epilogue (residual from smem A): even n = a, odd n = gate ----
    const __half* Asm = (const __half*)sm;
#pragma unroll
    for (int mt = 0; mt < 4; mt++) {
#pragma unroll
        for (int nt = 0; nt < 4; nt++) {
            int n = n0 + wc * 32 + nt * 8 + 2 * tig;
            int i = n >> 1;
#pragma unroll
            for (int half_ = 0; half_ < 2; half_++) {
                int mr = wr * 64 + mt * 16 + gid + half_ * 8;  // 0..127
                int m = m0 + mr;
                float a = acc[mt][nt][half_ * 2 + 0] + bias[i];
                float g = acc[mt][nt][half_ * 2 + 1] + bias[256 + i];
                float v = __half2float(Asm[(mr + 2) * 264 + i]) +
                          a * sigmoidf(g);
                if (MASKED && g_mask[m]) v = 0.f;
                C[(size_t)m * 256 + i] = __float2half_rn(v);
            }
        }
    }
}

// ---------------------------------------------------------------------------
// FP16 tensor-core TN GEMM: C = epi( A[M,K](lda) @ B[N,K](ldb)^T )
// 128x128 tile, BK=32, 256 threads, 4-stage cp.async (1 barrier/iter).
// EPI: 1=mish(+bias) half,
//      8=QKV fused (n<512 -> qk, n>=512 -> vt transpose; res=vt out),
//      9=Wo: +bias+res, masked pool directly into g_Sp (no C store)
// ---------------------------------------------------------------------------
template <int EPI>
__global__ void __launch_bounds__(256)
mma_gemm(const __half* __restrict__ A, const __half* __restrict__ Bm,
         const float* __restrict__ bias, const __half* __restrict__ res,
         void* __restrict__ Cv, int K, int lda, int ldb, int ldc) {
    extern __shared__ char sm[];             // A[4] then B[4]
    char* smB = sm + STAGES * TILE_B;
    const unsigned smA_s = (unsigned)__cvta_generic_to_shared(sm);
    const unsigned smB_s = smA_s + STAGES * TILE_B;

    const int m0 = blockIdx.y * 128;
    const int n0 = blockIdx.x * 128;
    const int tid  = threadIdx.x;
    const int warp = tid >> 5, lane = tid & 31;
    const int wr = warp >> 2, wc = warp & 3;     // 2 x 4 warp grid
    const int gid = lane >> 2, tig = lane & 3;

    const int lr8 = lane & 7;
    unsigned aoff[4], boff[2];
#pragma unroll
    for (int mt = 0; mt < 4; mt++)
        aoff[mt] = (unsigned)((wr * 64 + mt * 16 + lr8 + ((lane >> 3) & 1) * 8)
                   * ROW_B + ((lane >> 4) & 1) * 16);
#pragma unroll
    for (int np = 0; np < 2; np++)
        boff[np] = (unsigned)((wc * 32 + np * 16 + lr8 + ((lane >> 4) & 1) * 8)
                   * ROW_B + ((lane >> 3) & 1) * 16);

    auto load_tiles = [&](int buf, int kt) {
#pragma unroll
        for (int p = 0; p < 2; p++) {
            int idx = tid + p * 256;
            int row = idx >> 2, ch = idx & 3;
            cpa16(sm + buf * TILE_B + row * ROW_B + ch * 16,
                  A + (size_t)(m0 + row) * lda + kt + ch * 8);
            cpa16(smB + buf * TILE_B + row * ROW_B + ch * 16,
                  Bm + (size_t)(n0 + row) * ldb + kt + ch * 8);
        }
    };

    float acc[4][4][4];
#pragma unroll
    for (int i = 0; i < 4; i++)
#pragma unroll
        for (int j = 0; j < 4; j++)
#pragma unroll
            for (int q = 0; q < 4; q++) acc[i][j][q] = 0.f;

    const int nIter = K >> 5;                    // BK = 32 halves, nIter >= 4
    load_tiles(0, 0);
    asm volatile("cp.async.commit_group;" ::: "memory");
    load_tiles(1, 32);
    asm volatile("cp.async.commit_group;" ::: "memory");
    load_tiles(2, 64);
    asm volatile("cp.async.commit_group;" ::: "memory");

    for (int it = 0; it < nIter; it++) {
        int buf = it & 3;
        if (it + 2 < nIter) {
            asm volatile("cp.async.wait_group 2;" ::: "memory");
        } else if (it + 1 < nIter) {
            asm volatile("cp.async.wait_group 1;" ::: "memory");
        } else {
            asm volatile("cp.async.wait_group 0;" ::: "memory");
        }
        __syncthreads();
        if (it + 3 < nIter) {
            load_tiles((it + 3) & 3, (it + 3) << 5);
            asm volatile("cp.async.commit_group;" ::: "memory");
        }

        const unsigned baseA = smA_s + buf * TILE_B;
        const unsigned baseB = smB_s + buf * TILE_B;
#pragma unroll
        for (int ks = 0; ks < 2; ks++) {
            unsigned kb = ks * 32;
            unsigned af[4][4];
#pragma unroll
            for (int mt = 0; mt < 4; mt++)
                ldsm4(af[mt], baseA + kb + aoff[mt]);
            unsigned bfr[4][2];
#pragma unroll
            for (int np = 0; np < 2; np++) {
                unsigned bt[4];
                ldsm4(bt, baseB + kb + boff[np]);
                bfr[2 * np][0] = bt[0]; bfr[2 * np][1] = bt[1];
                bfr[2 * np + 1][0] = bt[2]; bfr[2 * np + 1][1] = bt[3];
            }
#pragma unroll
            for (int mt = 0; mt < 4; mt++)
#pragma unroll
                for (int nt = 0; nt < 4; nt++)
                    mma_f16(acc[mt][nt], af[mt], bfr[nt]);
        }
    }

    // ---- epilogue ----
    if (EPI == 9) {
        float ls[4][2];
#pragma unroll
        for (int nt = 0; nt < 4; nt++) { ls[nt][0] = 0.f; ls[nt][1] = 0.f; }
#pragma unroll
        for (int mt = 0; mt < 4; mt++)
#pragma unroll
            for (int half_ = 0; half_ < 2; half_++) {
                int m = m0 + wr * 64 + mt * 16 + gid + half_ * 8;
                bool keep = (g_mask[m] == 0);
#pragma unroll
                for (int nt = 0; nt < 4; nt++) {
                    int n = n0 + wc * 32 + nt * 8 + 2 * tig;
                    float v0 = acc[mt][nt][half_ * 2 + 0] + bias[n] +
                               __half2float(res[(size_t)m * ldc + n]);
                    float v1 = acc[mt][nt][half_ * 2 + 1] + bias[n + 1] +
                               __half2float(res[(size_t)m * ldc + n + 1]);
                    if (keep) { ls[nt][0] += v0; ls[nt][1] += v1; }
                }
            }
#pragma unroll
        for (int nt = 0; nt < 4; nt++)
#pragma unroll
            for (int c = 0; c < 2; c++) {
                float r = ls[nt][c];
                r += __shfl_xor_sync(0xffffffffu, r, 4);
                r += __shfl_xor_sync(0xffffffffu, r, 8);
                r += __shfl_xor_sync(0xffffffffu, r, 16);
                ls[nt][c] = r;
            }
        __syncthreads();
        float* spf = (float*)sm;
        if (lane < 4) {
#pragma unroll
            for (int nt = 0; nt < 4; nt++) {
                spf[warp * 32 + lane * 8 + nt * 2 + 0] = ls[nt][0];
                spf[warp * 32 + lane * 8 + nt * 2 + 1] = ls[nt][1];
            }
        }
        __syncthreads();
        if (warp < 4) {
            float s = spf[warp * 32 + lane] + spf[(warp + 4) * 32 + lane];
            int tig_ = lane >> 3, nt_ = (lane >> 1) & 3, c_ = lane & 1;
            int n = n0 + warp * 32 + nt_ * 8 + 2 * tig_ + c_;
            int y = m0 >> 7, b = y >> 3, chunk = y & 7;
            g_Sp[chunk][b * Dn + n] = s;
        }
        return;
    }

#pragma unroll
    for (int mt = 0; mt < 4; mt++) {
#pragma unroll
        for (int nt = 0; nt < 4; nt++) {
            int mbase = m0 + wr * 64 + mt * 16 + gid;
            int n = n0 + wc * 32 + nt * 8 + 2 * tig;
#pragma unroll
            for (int half_ = 0; half_ < 2; half_++) {
                int m = mbase + half_ * 8;
                float v0 = acc[mt][nt][half_ * 2 + 0];
                float v1 = acc[mt][nt][half_ * 2 + 1];
                if (EPI == 8) {
                    v0 += bias[n]; v1 += bias[n + 1];
                    if (n0 < 512) {              // q,k region
                        __half* C = (__half*)Cv;
                        *(__half2*)(C + (size_t)m * 512 + n) =
                            __floats2half2_rn(v0, v1);
                    } else {                     // v region -> transposed store
                        __half* VT = (__half*)(void*)res;
                        int bb = m >> 10, t = m & (Tn - 1);
                        int d = n - 512;
                        VT[((size_t)((bb * 2 + (d >> 7)) * 128 + (d & 127))) * Tn + t] =
                            __float2half_rn(v0);
                        d = n + 1 - 512;
                        VT[((size_t)((bb * 2 + (d >> 7)) * 128 + (d & 127))) * Tn + t] =
                            __float2half_rn(v1);
                    }
                } else {                          // EPI == 1 (mish)
                    __half* C = (__half*)Cv;
                    v0 = mishf(v0 + bias[n]);
                    v1 = mishf(v1 + bias[n + 1]);
                    *(__half2*)(C + (size_t)m * ldc + n) =
                        __floats2half2_rn(v0, v1);
                }
            }
        }
    }
}

// ---------------------------------------------------------------------------
// Fused attention (no-max flash). Grid (8 q-tiles, 32 bh), 256 threads.
// exp via ex2.approx.f16x2 (mask multiplicative from smem halves); rowsum via
// appended ones column of V (n-tile 8, col 128), fp32 from PV matmul.
// ---------------------------------------------------------------------------
__global__ void __launch_bounds__(256)
flash_kernel(const __half* __restrict__ qk, const __half* __restrict__ vt,
             __half* __restrict__ attn) {
    const int qt = blockIdx.x;
    const int z  = blockIdx.y;
    const int zb = z >> 1, zh = z & 1;
    extern __shared__ char sm[];
    const unsigned smQ = (unsigned)__cvta_generic_to_shared(sm);
    const int tid = threadIdx.x, warp = tid >> 5, lane = tid & 31;
    const int gid = lane >> 2, tig = lane & 3, lr8 = lane & 7;

    const unsigned aoffQ = (unsigned)((warp * 16 + lr8 + ((lane >> 3) & 1) * 8)
                           * FROW_B + ((lane >> 4) & 1) * 16);
    unsigned boffF[9];
#pragma unroll
    for (int np = 0; np < 9; np++)
        boffF[np] = (unsigned)((np * 16 + lr8 + ((lane >> 4) & 1) * 8)
                    * FROW_B + ((lane >> 3) & 1) * 16);

    auto loadQ = [&]() {
#pragma unroll
        for (int p = 0; p < 8; p++) {
            int idx = tid + p * 256;
            int row = idx >> 4, ch = idx & 15;
            cpa16(sm + row * FROW_B + ch * 16,
                  qk + (size_t)(zb * Tn + qt * 128 + row) * 512 +
                  zh * 128 + ch * 8);
        }
    };
    auto loadK = [&](int buf, int jt) {
#pragma unroll
        for (int p = 0; p < 8; p++) {
            int idx = tid + p * 256;
            int row = idx >> 4, ch = idx & 15;
            cpa16(sm + FK_OFF + buf * FTILE_B + row * FROW_B + ch * 16,
                  qk + (size_t)(zb * Tn + jt * 128 + row) * 512 +
                  256 + zh * 128 + ch * 8);
        }
    };
    auto loadV = [&](int buf, int jt) {
#pragma unroll
        for (int p = 0; p < 8; p++) {
            int idx = tid + p * 256;
            int row = idx >> 4, ch = idx & 15;
            cpa16(sm + FV_OFF + buf * FVTILE_B + row * FROW_B + ch * 16,
                  vt + (size_t)(z * 128 + row) * Tn + jt * 128 + ch * 8);
        }
    };

    // V rows 128-143 (both buffers): row 128 = ones (rowsum col), rest zero.
    {
        const uint4 ones = make_uint4(0x3C003C00u, 0x3C003C00u,
                                      0x3C003C00u, 0x3C003C00u);
        const uint4 zero = make_uint4(0u, 0u, 0u, 0u);
        for (int i = tid; i < 2 * 16 * 17; i += 256) {
            int buf = i / 272;
            int rem = i - buf * 272;
            int r = rem / 17, ch = rem - r * 17;
            uint4 v = (r == 0 && ch < 16) ? ones : zero;
            *(uint4*)(sm + FV_OFF + buf * FVTILE_B + (128 + r) * FROW_B +
                      ch * 16) = v;
        }
    }
    // key-mask halves (1024) into smem
    if (tid < 128)
        cpa16(sm + MASK_OFF + tid * 16, g_maskh + zb * Tn + tid * 8);

    loadQ(); loadK(0, 0); loadV(0, 0);
    asm volatile("cp.async.commit_group;" ::: "memory");

    float O[18][4];
#pragma unroll
    for (int i = 0; i < 18; i++)
#pragma unroll
        for (int q = 0; q < 4; q++) O[i][q] = 0.f;
    unsigned qf[8][4];
    const __half2 LIM2 = __floats2half2_rn(15.f, 15.f);

    for (int jt = 0; jt < 8; jt++) {
        int buf = jt & 1;
        asm volatile("cp.async.wait_group 0;" ::: "memory");
        __syncthreads();
        if (jt < 7) {
            loadK(buf ^ 1, jt + 1);
            loadV(buf ^ 1, jt + 1);
            asm volatile("cp.async.commit_group;" ::: "memory");
        }
        if (jt == 0) {
#pragma unroll
            for (int kd = 0; kd < 8; kd++)
                ldsm4(qf[kd], smQ + kd * 32 + aoffQ);
        }

        // ---- S = Q . K^T ----
        float S[16][4];
#pragma unroll
        for (int i = 0; i < 16; i++)
#pragma unroll
            for (int q = 0; q < 4; q++) S[i][q] = 0.f;
        const unsigned baseK = smQ + FK_OFF + buf * FTILE_B;
#pragma unroll
        for (int kd = 0; kd < 8; kd++) {
#pragma unroll
            for (int np = 0; np < 8; np++) {
                unsigned bt[4];
                ldsm4(bt, baseK + kd * 32 + boffF[np]);
                mma_f16(S[2 * np],     qf[kd], bt);
                mma_f16(S[2 * np + 1], qf[kd], bt + 2);
            }
        }

        // ---- P = 2^(S*scale*log2e) * mask   (f16x2 path) ----
        unsigned P[16][2];
        const __half2* mh2 = (const __half2*)(sm + MASK_OFF + jt * 256);
#pragma unroll
        for (int nt = 0; nt < 16; nt++) {
            __half2 m2 = mh2[nt * 4 + tig];
            __half2 x0 = __floats2half2_rn(S[nt][0] * CL2E, S[nt][1] * CL2E);
            __half2 x1 = __floats2half2_rn(S[nt][2] * CL2E, S[nt][3] * CL2E);
            x0 = __hmin2(x0, LIM2);
            x1 = __hmin2(x1, LIM2);
            unsigned e0 = ex2h2(*(unsigned*)&x0);
            unsigned e1 = ex2h2(*(unsigned*)&x1);
            __half2 p0 = __hmul2(*(__half2*)&e0, m2);
            __half2 p1 = __hmul2(*(__half2*)&e1, m2);
            P[nt][0] = *(unsigned*)&p0;
            P[nt][1] = *(unsigned*)&p1;
        }

        // ---- O += P . V^T  (incl. ones column -> rowsum in O[16]) ----
        const unsigned baseV = smQ + FV_OFF + buf * FVTILE_B;
#pragma unroll
        for (int s = 0; s < 8; s++) {
            unsigned a2[4] = { P[2 * s][0], P[2 * s][1],
                               P[2 * s + 1][0], P[2 * s + 1][1] };
#pragma unroll
            for (int np = 0; np < 9; np++) {
                unsigned bt[4];
                ldsm4(bt, baseV + s * 32 + boffF[np]);
                mma_f16(O[2 * np],     a2, bt);
                if (np < 8)
                    mma_f16(O[2 * np + 1], a2, bt + 2);
            }
        }
    }

    // rowsum lives in col 128 = O[16][0]/O[16][2] on tig==0 lanes
    float rs0 = __shfl_sync(0xffffffffu, O[16][0], lane & 28);
    float rs1 = __shfl_sync(0xffffffffu, O[16][2], lane & 28);
    float i0 = 1.f / rs0, i1 = 1.f / rs1;
    int t = qt * 128 + warp * 16 + gid;
    __half* dst = attn + (size_t)(zb * Tn + t) * 256 + zh * 128;
#pragma unroll
    for (int nt = 0; nt < 16; nt++) {
        int d = nt * 8 + 2 * tig;
        *(__half2*)(dst + d) = __floats2half2_rn(O[nt][0] * i0, O[nt][1] * i0);
        *(__half2*)(dst + (size_t)8 * 256 + d) =
            __floats2half2_rn(O[nt][2] * i1, O[nt][3] * i1);
    }
}

// out[b,n] = (S_b @ Wf^T)[n]/len_b + bf[n]
__global__ void final_kernel(const float* __restrict__ Wf,
                             const float* __restrict__ bf,
                             float* __restrict__ out) {
    int b = blockIdx.x;
    int n = threadIdx.x;
    __shared__ float sb[Dn];
    float s = 0.f;
#pragma unroll
    for (int c = 0; c < 8; c++) s += g_Sp[c][b * Dn + n];
    sb[n] = s;
    __syncthreads();
    float acc = 0.f;
    const float* w = Wf + (size_t)n * Dn;
#pragma unroll 8
    for (int k = 0; k < Dn; k++) acc = fmaf(sb[k], w[k], acc);
    out[b * Dn + n] = acc * g_cinv[b] + bf[n];
}

// ---------------------------------------------------------------------------
extern "C" void kernel_launch(void* const* d_in, const int* in_sizes, int n_in,
                              void* d_out, int out_size) {
    (void)in_sizes; (void)n_in; (void)out_size;
    const float* x   = (const float*)d_in[0];
    const unsigned char* mraw = (const unsigned char*)d_in[1];
    const float* W1  = (const float*)d_in[2];
    const float* b1  = (const float*)d_in[3];
    const float* W2  = (const float*)d_in[4];
    const float* b2  = (const float*)d_in[5];
    const float* cW1 = (const float*)d_in[6];
    const float* cb1 = (const float*)d_in[7];
    const float* cW2 = (const float*)d_in[8];
    const float* cb2 = (const float*)d_in[9];
    const float* Wq  = (const float*)d_in[10];
    const float* bq  = (const float*)d_in[11];
    const float* Wk  = (const float*)d_in[12];
    const float* bk  = (const float*)d_in[13];
    const float* Wv  = (const float*)d_in[14];
    const float* bv  = (const float*)d_in[15];
    const float* Wo  = (const float*)d_in[16];
    const float* bo  = (const float*)d_in[17];
    const float* Wf  = (const float*)d_in[18];
    const float* bf  = (const float*)d_in[19];
    float* out = (float*)d_out;

    __half *xh, *h1, *h2, *h3, *res, *qk, *vt, *attn;
    __half *wt1, *wt2, *w1h, *w2h, *woh, *wqkv;
    float *bqkv;
    cudaGetSymbolAddress((void**)&xh, g_xh);
    cudaGetSymbolAddress((void**)&h1, g_h1);
    cudaGetSymbolAddress((void**)&h2, g_h2);
    cudaGetSymbolAddress((void**)&h3, g_h3);
    cudaGetSymbolAddress((void**)&res, g_res);
    cudaGetSymbolAddress((void**)&qk, g_qk);
    cudaGetSymbolAddress((void**)&vt, g_vt);
    cudaGetSymbolAddress((void**)&attn, g_attn);
    cudaGetSymbolAddress((void**)&wt1, g_wt1);
    cudaGetSymbolAddress((void**)&wt2, g_wt2);
    cudaGetSymbolAddress((void**)&w1h, g_w1h);
    cudaGetSymbolAddress((void**)&w2h, g_w2h);
    cudaGetSymbolAddress((void**)&woh, g_woh);
    cudaGetSymbolAddress((void**)&wqkv, g_wqkv);
    cudaGetSymbolAddress((void**)&bqkv, g_bqkv);

    cudaFuncSetAttribute(mma_gemm<1>, cudaFuncAttributeMaxDynamicSharedMemorySize, SMEM_SZ);
    cudaFuncSetAttribute(mma_gemm<8>, cudaFuncAttributeMaxDynamicSharedMemorySize, SMEM_SZ);
    cudaFuncSetAttribute(mma_gemm<9>, cudaFuncAttributeMaxDynamicSharedMemorySize, SMEM_SZ);
    cudaFuncSetAttribute(conv_gemm<false>, cudaFuncAttributeMaxDynamicSharedMemorySize, CSMEM);
    cudaFuncSetAttribute(conv_gemm<true>,  cudaFuncAttributeMaxDynamicSharedMemorySize, CSMEM);
    cudaFuncSetAttribute(flash_kernel, cudaFuncAttributeMaxDynamicSharedMemorySize, FSMEM);

    // 0) single merged prep pass (incl. mask normalization block)
    prep_all<<<7361, 256>>>(x, W1, W2, Wo, Wq, Wk, Wv, bq, bk, bv,
                            cW1, cW2, mraw);

    dim3 gDense(2, 128, 1);
    dim3 gConv(4, 128, 1);
    dim3 gQKV(6, 128, 1);
    dim3 gFlash(8, 32, 1);

    // 1) spectral MLP (Linear + Mish) x2
    mma_gemm<1><<<gDense, 256, SMEM_SZ>>>(xh, w1h, b1, nullptr, h1,
        Dn, Dn, Dn, Dn);
    mma_gemm<1><<<gDense, 256, SMEM_SZ>>>(h1, w2h, b2, nullptr, h2,
        Dn, Dn, Dn, Dn);

    // 2) Conv1dGLU x2 (resident-A conv kernel, GLU fused, residual from smem)
    conv_gemm<false><<<gConv, 256, CSMEM>>>(h2, wt1, cb1, h3);
    conv_gemm<true><<<gConv, 256, CSMEM>>>(h3, wt2, cb2, res);

    // 3) fused q,k,v projection (N=768; v written transposed via res ptr)
    mma_gemm<8><<<gQKV, 256, SMEM_SZ>>>(res, wqkv, bqkv, vt, qk,
        Dn, Dn, Dn, 512);

    // 4) fused attention (flash, no-max, f16x2 exp, ones-column rowsum)
    flash_kernel<<<gFlash, 256, FSMEM>>>(qk, vt, attn);

    // 5) output projection + residual with fused masked pool (no h5 store)
    mma_gemm<9><<<gDense, 256, SMEM_SZ>>>(attn, woh, bo, res, nullptr,
        Dn, Dn, Dn, Dn);

    // 6) tiny final GEMM (Wf applied to pooled sums)
    final_kernel<<<Bn, Dn>>>(Wf, bf, out);
}